// round 1
// baseline (speedup 1.0000x reference)
#include <cuda_runtime.h>
#include <cstddef>

// Problem constants (fixed by reference): B=32, C=512, H=W=32 -> N=1024, 32 groups
#define BATCH 32
#define CH    512
#define NPIX  1024
#define NG    32
#define CPG   (CH / NG)   // 16 channels per group
#define EPS   1e-6f

// ---------------------------------------------------------------------------
// Scratch (device globals — no runtime allocation allowed)
// ---------------------------------------------------------------------------
__device__ float g_H[(size_t)BATCH * CH * NPIX];      // 64 MB  groupnorm output [B][C][N]
__device__ float g_Q[(size_t)BATCH * CH * NPIX];      // 64 MB  [B][C][N]
__device__ float g_K[(size_t)BATCH * CH * NPIX];      // 64 MB  [B][C][N]
__device__ float g_V[(size_t)BATCH * CH * NPIX];      // 64 MB  [B][C][N]
__device__ float g_S[(size_t)BATCH * NPIX * NPIX];    // 128 MB [B][Nq][Nk]
__device__ float g_O[(size_t)BATCH * CH * NPIX];      // 64 MB  [B][C][N]

// ---------------------------------------------------------------------------
// GroupNorm: one block per (batch, group). 16 ch x 1024 px = 16384 elems.
// ---------------------------------------------------------------------------
__global__ __launch_bounds__(256) void groupnorm_kernel(
    const float* __restrict__ x,
    const float* __restrict__ w,
    const float* __restrict__ b,
    float* __restrict__ h)
{
    const int bg    = blockIdx.x;
    const int batch = bg / NG;
    const int g     = bg % NG;
    const size_t base = ((size_t)batch * CH + (size_t)g * CPG) * NPIX;
    const float* xp = x + base;
    float* hp = h + base;
    const int COUNT = CPG * NPIX; // 16384

    float s = 0.f, ss = 0.f;
    for (int i = threadIdx.x; i < COUNT; i += 256) {
        float v = xp[i];
        s  += v;
        ss += v * v;
    }
    __shared__ float sh_s[256];
    __shared__ float sh_ss[256];
    sh_s[threadIdx.x]  = s;
    sh_ss[threadIdx.x] = ss;
    __syncthreads();
    for (int st = 128; st > 0; st >>= 1) {
        if (threadIdx.x < st) {
            sh_s[threadIdx.x]  += sh_s[threadIdx.x + st];
            sh_ss[threadIdx.x] += sh_ss[threadIdx.x + st];
        }
        __syncthreads();
    }
    const float mean = sh_s[0] * (1.0f / COUNT);
    const float var  = sh_ss[0] * (1.0f / COUNT) - mean * mean;
    const float inv  = rsqrtf(var + EPS);

    for (int i = threadIdx.x; i < COUNT; i += 256) {
        int c = g * CPG + (i >> 10);     // i / NPIX
        float v = (xp[i] - mean) * inv;
        hp[i] = v * w[c] + b[c];
    }
}

// ---------------------------------------------------------------------------
// Generic batched SGEMM: C[m][n] = alpha * sum_k A(m,k)*B(k,n) + bias[m] + resid
//   TA=0: A stored [M][K] row-major;  TA=1: A stored [K][M]
//   TB=0: B stored [K][N] row-major;  TB=1: B stored [N][K]
// Tile: 128x128x8, 256 threads, 8x8 per thread. All dims divide evenly here.
// ---------------------------------------------------------------------------
template<bool TA, bool TB>
__global__ __launch_bounds__(256) void gemm_kernel(
    const float* __restrict__ A,
    const float* __restrict__ B,
    float* __restrict__ C,
    int M, int N, int K,
    size_t sA, size_t sB, size_t sC,
    const float* __restrict__ bias,
    const float* __restrict__ resid, size_t sR,
    float alpha)
{
    __shared__ float As[8][132];
    __shared__ float Bs[8][132];

    const int bz = blockIdx.z;
    A += (size_t)bz * sA;
    B += (size_t)bz * sB;
    C += (size_t)bz * sC;

    const int tid = threadIdx.x;
    const int tx  = tid & 15;   // 0..15 -> n
    const int ty  = tid >> 4;   // 0..15 -> m
    const int m0  = blockIdx.y * 128;
    const int n0  = blockIdx.x * 128;

    float acc[8][8] = {};

    for (int k0 = 0; k0 < K; k0 += 8) {
        // ---- load A tile into As[k][m] ----
        if (TA) {
            // A is [K][M]: coalesced along m
            #pragma unroll
            for (int i = 0; i < 4; i++) {
                int idx = tid + i * 256;
                int k = idx >> 7, m = idx & 127;
                As[k][m] = A[(size_t)(k0 + k) * M + m0 + m];
            }
        } else {
            // A is [M][K]
            #pragma unroll
            for (int i = 0; i < 4; i++) {
                int idx = tid + i * 256;
                int m = idx >> 3, k = idx & 7;
                As[k][m] = A[(size_t)(m0 + m) * K + k0 + k];
            }
        }
        // ---- load B tile into Bs[k][n] ----
        if (TB) {
            // B is [N][K]
            #pragma unroll
            for (int i = 0; i < 4; i++) {
                int idx = tid + i * 256;
                int n = idx >> 3, k = idx & 7;
                Bs[k][n] = B[(size_t)(n0 + n) * K + k0 + k];
            }
        } else {
            // B is [K][N]: coalesced along n
            #pragma unroll
            for (int i = 0; i < 4; i++) {
                int idx = tid + i * 256;
                int k = idx >> 7, n = idx & 127;
                Bs[k][n] = B[(size_t)(k0 + k) * N + n0 + n];
            }
        }
        __syncthreads();

        #pragma unroll
        for (int k = 0; k < 8; k++) {
            float a[8], bb[8];
            #pragma unroll
            for (int i = 0; i < 8; i++) a[i]  = As[k][ty * 8 + i];
            #pragma unroll
            for (int j = 0; j < 8; j++) bb[j] = Bs[k][tx * 8 + j];
            #pragma unroll
            for (int i = 0; i < 8; i++)
                #pragma unroll
                for (int j = 0; j < 8; j++)
                    acc[i][j] += a[i] * bb[j];
        }
        __syncthreads();
    }

    // ---- epilogue ----
    #pragma unroll
    for (int i = 0; i < 8; i++) {
        const int m = m0 + ty * 8 + i;
        const float bv = bias ? bias[m] : 0.f;
        #pragma unroll
        for (int j = 0; j < 8; j++) {
            const int n = n0 + tx * 8 + j;
            float v = acc[i][j] * alpha + bv;
            if (resid) v += resid[(size_t)bz * sR + (size_t)m * N + n];
            C[(size_t)m * N + n] = v;
        }
    }
}

// ---------------------------------------------------------------------------
// Row softmax over S[b][q][:], row length 1024. One block per row.
// ---------------------------------------------------------------------------
__global__ __launch_bounds__(256) void softmax_kernel(float* __restrict__ S)
{
    float* p = S + (size_t)blockIdx.x * NPIX;
    const int t = threadIdx.x;

    float v[4];
    float mx = -1e30f;
    #pragma unroll
    for (int i = 0; i < 4; i++) {
        v[i] = p[t + i * 256];
        mx = fmaxf(mx, v[i]);
    }
    __shared__ float red[256];
    red[t] = mx;
    __syncthreads();
    for (int st = 128; st > 0; st >>= 1) {
        if (t < st) red[t] = fmaxf(red[t], red[t + st]);
        __syncthreads();
    }
    mx = red[0];
    __syncthreads();

    float sum = 0.f;
    #pragma unroll
    for (int i = 0; i < 4; i++) {
        v[i] = __expf(v[i] - mx);
        sum += v[i];
    }
    red[t] = sum;
    __syncthreads();
    for (int st = 128; st > 0; st >>= 1) {
        if (t < st) red[t] += red[t + st];
        __syncthreads();
    }
    const float inv = 1.0f / red[0];
    #pragma unroll
    for (int i = 0; i < 4; i++) p[t + i * 256] = v[i] * inv;
}

// ---------------------------------------------------------------------------
// Launch
// ---------------------------------------------------------------------------
extern "C" void kernel_launch(void* const* d_in, const int* in_sizes, int n_in,
                              void* d_out, int out_size)
{
    (void)in_sizes; (void)n_in; (void)out_size;
    const float* x    = (const float*)d_in[0];
    const float* gn_w = (const float*)d_in[1];
    const float* gn_b = (const float*)d_in[2];
    const float* wq   = (const float*)d_in[3];
    const float* bq   = (const float*)d_in[4];
    const float* wk   = (const float*)d_in[5];
    const float* bk   = (const float*)d_in[6];
    const float* wv   = (const float*)d_in[7];
    const float* bv   = (const float*)d_in[8];
    const float* wp   = (const float*)d_in[9];
    const float* bp   = (const float*)d_in[10];
    float* out = (float*)d_out;

    float *H, *Q, *K, *V, *S, *O;
    cudaGetSymbolAddress((void**)&H, g_H);
    cudaGetSymbolAddress((void**)&Q, g_Q);
    cudaGetSymbolAddress((void**)&K, g_K);
    cudaGetSymbolAddress((void**)&V, g_V);
    cudaGetSymbolAddress((void**)&S, g_S);
    cudaGetSymbolAddress((void**)&O, g_O);

    const size_t sCN = (size_t)CH * NPIX;     // 524288
    const size_t sNN = (size_t)NPIX * NPIX;   // 1048576
    const float scale = 0.044194173824159223f; // 512^-0.5

    // 1) GroupNorm
    groupnorm_kernel<<<BATCH * NG, 256>>>(x, gn_w, gn_b, H);

    // 2) Q/K/V projections: Y[b][o][n] = W[o][c] * H[b][c][n] + bias[o]
    {
        dim3 grid(NPIX / 128, CH / 128, BATCH); // (8,4,32)
        gemm_kernel<false, false><<<grid, 256>>>(wq, H, Q, CH, NPIX, CH,
                                                 0, sCN, sCN, bq, nullptr, 0, 1.f);
        gemm_kernel<false, false><<<grid, 256>>>(wk, H, K, CH, NPIX, CH,
                                                 0, sCN, sCN, bk, nullptr, 0, 1.f);
        gemm_kernel<false, false><<<grid, 256>>>(wv, H, V, CH, NPIX, CH,
                                                 0, sCN, sCN, bv, nullptr, 0, 1.f);
    }

    // 3) Scores: S[b][q][k] = scale * sum_c Q[b][c][q] * K[b][c][k]   (TN)
    {
        dim3 grid(NPIX / 128, NPIX / 128, BATCH); // (8,8,32)
        gemm_kernel<true, false><<<grid, 256>>>(Q, K, S, NPIX, NPIX, CH,
                                                sCN, sCN, sNN, nullptr, nullptr, 0, scale);
    }

    // 4) Softmax rows
    softmax_kernel<<<BATCH * NPIX, 256>>>(S);

    // 5) O[b][c][n] = sum_m V[b][c][m] * S[b][n][m]   (NT)
    {
        dim3 grid(NPIX / 128, CH / 128, BATCH); // (8,4,32)
        gemm_kernel<false, true><<<grid, 256>>>(V, S, O, CH, NPIX, NPIX,
                                                sCN, sNN, sCN, nullptr, nullptr, 0, 1.f);
    }

    // 6) out = x + Wp * O + bp
    {
        dim3 grid(NPIX / 128, CH / 128, BATCH); // (8,4,32)
        gemm_kernel<false, false><<<grid, 256>>>(wp, O, out, CH, NPIX, CH,
                                                 0, sCN, sCN, bp, x, sCN, 1.f);
    }
}

// round 2
// speedup vs baseline: 2.5323x; 2.5323x over previous
#include <cuda_runtime.h>
#include <cuda_bf16.h>
#include <cstdint>
#include <cstddef>

// Problem constants: B=32, C=512, H=W=32 -> N=1024, 32 groups
#define BATCH 32
#define CH    512
#define NPIX  1024
#define NG    32
#define CPG   (CH / NG)
#define EPS   1e-6f

// ---------------------------------------------------------------------------
// Scratch (device globals — no runtime allocation allowed)
// ---------------------------------------------------------------------------
__device__ float g_H[(size_t)BATCH * CH * NPIX];      // groupnorm output [B][C][N]
__device__ float g_Q[(size_t)BATCH * CH * NPIX];      // [B][C][N]
__device__ float g_K[(size_t)BATCH * CH * NPIX];      // [B][C][N]
__device__ float g_V[(size_t)BATCH * CH * NPIX];      // [B][C][N]
__device__ float g_S[(size_t)BATCH * NPIX * NPIX];    // [B][Nq][Nk]
__device__ float g_O[(size_t)BATCH * CH * NPIX];      // [B][C][N]

// ---------------------------------------------------------------------------
// Helpers
// ---------------------------------------------------------------------------
__device__ __forceinline__ uint32_t smem_u32(const void* p) {
    return (uint32_t)__cvta_generic_to_shared(p);
}

__device__ __forceinline__ void ldsm4(uint32_t r[4], uint32_t a) {
    asm volatile("ldmatrix.sync.aligned.m8n8.x4.shared.b16 {%0,%1,%2,%3}, [%4];"
        : "=r"(r[0]), "=r"(r[1]), "=r"(r[2]), "=r"(r[3]) : "r"(a));
}

__device__ __forceinline__ void mma16816(float d[4], const uint32_t a[4], const uint32_t* b) {
    asm volatile(
        "mma.sync.aligned.m16n8k16.row.col.f32.bf16.bf16.f32 "
        "{%0,%1,%2,%3}, {%4,%5,%6,%7}, {%8,%9}, {%0,%1,%2,%3};"
        : "+f"(d[0]), "+f"(d[1]), "+f"(d[2]), "+f"(d[3])
        : "r"(a[0]), "r"(a[1]), "r"(a[2]), "r"(a[3]), "r"(b[0]), "r"(b[1]));
}

// split fp32 pair -> (hi bf16x2, lo bf16x2)
__device__ __forceinline__ void split2(float a, float b, uint32_t& h, uint32_t& l) {
    __nv_bfloat162 hh = __floats2bfloat162_rn(a, b);
    float ra = a - __bfloat162float(hh.x);
    float rb = b - __bfloat162float(hh.y);
    __nv_bfloat162 ll = __floats2bfloat162_rn(ra, rb);
    h = *reinterpret_cast<uint32_t*>(&hh);
    l = *reinterpret_cast<uint32_t*>(&ll);
}

// ---------------------------------------------------------------------------
// GroupNorm: one block per (batch, group)
// ---------------------------------------------------------------------------
__global__ __launch_bounds__(256) void groupnorm_kernel(
    const float* __restrict__ x, const float* __restrict__ w,
    const float* __restrict__ b, float* __restrict__ h)
{
    const int bg = blockIdx.x;
    const int batch = bg / NG;
    const int g = bg % NG;
    const size_t base = ((size_t)batch * CH + (size_t)g * CPG) * NPIX;
    const float* xp = x + base;
    float* hp = h + base;
    const int COUNT = CPG * NPIX;

    float s = 0.f, ss = 0.f;
    for (int i = threadIdx.x; i < COUNT; i += 256) {
        float v = xp[i];
        s += v; ss += v * v;
    }
    __shared__ float sh_s[256], sh_ss[256];
    sh_s[threadIdx.x] = s; sh_ss[threadIdx.x] = ss;
    __syncthreads();
    for (int st = 128; st > 0; st >>= 1) {
        if (threadIdx.x < st) {
            sh_s[threadIdx.x]  += sh_s[threadIdx.x + st];
            sh_ss[threadIdx.x] += sh_ss[threadIdx.x + st];
        }
        __syncthreads();
    }
    const float mean = sh_s[0] * (1.0f / COUNT);
    const float var  = sh_ss[0] * (1.0f / COUNT) - mean * mean;
    const float inv  = rsqrtf(var + EPS);

    for (int i = threadIdx.x; i < COUNT; i += 256) {
        int c = g * CPG + (i >> 10);
        float v = (xp[i] - mean) * inv;
        hp[i] = v * w[c] + b[c];
    }
}

// ---------------------------------------------------------------------------
// Operand fetch: T=false -> gmem row-major [rows][K] (k contiguous, ld = K)
//                T=true  -> gmem [K][rows]  (rows contiguous, ld = row count)
// Tile is 128 rows x 32 k. 256 threads.
// ---------------------------------------------------------------------------
template<bool T>
struct Fetch {
    float4 v4[4];   // direct mode payload
    float2 vp[8];   // transposed mode payload

    __device__ __forceinline__ void load(const float* __restrict__ P,
                                         int r0, int k0, int ld, int tid) {
        if constexpr (T) {
            #pragma unroll
            for (int i = 0; i < 8; i++) {
                int p = tid + i * 256;       // 0..2047
                int m = p & 127;
                int k = (p >> 7) * 2;        // 0,2,..,30
                const float* b = P + (size_t)(k0 + k) * ld + r0 + m;
                vp[i].x = b[0];
                vp[i].y = b[ld];
            }
        } else {
            #pragma unroll
            for (int i = 0; i < 4; i++) {
                int idx = tid + i * 256;     // 0..1023
                int r = idx >> 3;
                int k4 = (idx & 7) << 2;
                v4[i] = *(const float4*)(P + (size_t)(r0 + r) * ld + k0 + k4);
            }
        }
    }

    __device__ __forceinline__ void store(__nv_bfloat16 (*dh)[40],
                                          __nv_bfloat16 (*dl)[40], int tid) {
        if constexpr (T) {
            #pragma unroll
            for (int i = 0; i < 8; i++) {
                int p = tid + i * 256;
                int m = p & 127;
                int k = (p >> 7) * 2;
                uint32_t h, l;
                split2(vp[i].x, vp[i].y, h, l);
                *(uint32_t*)&dh[m][k] = h;
                *(uint32_t*)&dl[m][k] = l;
            }
        } else {
            #pragma unroll
            for (int i = 0; i < 4; i++) {
                int idx = tid + i * 256;
                int r = idx >> 3;
                int k4 = (idx & 7) << 2;
                uint32_t h0, l0, h1, l1;
                split2(v4[i].x, v4[i].y, h0, l0);
                split2(v4[i].z, v4[i].w, h1, l1);
                uint2 hh; hh.x = h0; hh.y = h1;
                uint2 ll; ll.x = l0; ll.y = l1;
                *(uint2*)&dh[r][k4] = hh;
                *(uint2*)&dl[r][k4] = ll;
            }
        }
    }
};

// ---------------------------------------------------------------------------
// Batched GEMM via bf16-split tensor-core MMA (full fp32 accuracy):
//   C[m][n] = alpha * sum_k A'(m,k) * B'(n,k) + bias[m] (+ resid)
// TA/TB: operand stored transposed in gmem (see Fetch<T>).
// Block tile 128x128, k-tile 32, 8 warps (2 m x 4 n), warp tile 64x32.
// ---------------------------------------------------------------------------
template<bool TA, bool TB>
__global__ __launch_bounds__(256) void mma_gemm(
    const float* __restrict__ A, const float* __restrict__ B, float* __restrict__ C,
    int M, int N, int K, int ldA, int ldB,
    size_t sA, size_t sB, size_t sC,
    const float* __restrict__ bias,
    const float* __restrict__ resid, size_t sR,
    float alpha)
{
    __shared__ __align__(16) __nv_bfloat16 Ah[128][40];
    __shared__ __align__(16) __nv_bfloat16 Al[128][40];
    __shared__ __align__(16) __nv_bfloat16 Bh[128][40];
    __shared__ __align__(16) __nv_bfloat16 Bl[128][40];

    const int bz = blockIdx.z;
    A += (size_t)bz * sA;
    B += (size_t)bz * sB;
    C += (size_t)bz * sC;

    const int tid  = threadIdx.x;
    const int lane = tid & 31;
    const int warp = tid >> 5;
    const int wm = (warp >> 2) * 64;   // warp m offset within block tile
    const int wn = (warp & 3) * 32;    // warp n offset
    const int m0 = blockIdx.y * 128;
    const int n0 = blockIdx.x * 128;

    float acc[4][4][4] = {};

    Fetch<TA> fa;
    Fetch<TB> fb;
    fa.load(A, m0, 0, ldA, tid);
    fb.load(B, n0, 0, ldB, tid);

    for (int k0 = 0; k0 < K; k0 += 32) {
        fa.store(Ah, Al, tid);
        fb.store(Bh, Bl, tid);
        __syncthreads();

        if (k0 + 32 < K) {
            fa.load(A, m0, k0 + 32, ldA, tid);
            fb.load(B, n0, k0 + 32, ldB, tid);
        }

        #pragma unroll
        for (int kk = 0; kk < 32; kk += 16) {
            uint32_t ah[4][4], al[4][4];
            uint32_t bh[8], bl[8];

            // A fragments: row = wm + i*16 + (lane&15), col = kk + (lane>>4)*8
            const int ar = (lane & 15);
            const int ac = kk + (lane >> 4) * 8;
            #pragma unroll
            for (int i = 0; i < 4; i++) {
                ldsm4(ah[i], smem_u32(&Ah[wm + i * 16 + ar][ac]));
                ldsm4(al[i], smem_u32(&Al[wm + i * 16 + ar][ac]));
            }
            // B fragments (2 n-tiles per x4):
            // row = wn + jj*16 + (lane&7) + (lane>>4)*8, col = kk + ((lane>>3)&1)*8
            const int br = (lane & 7) + (lane >> 4) * 8;
            const int bc = kk + ((lane >> 3) & 1) * 8;
            #pragma unroll
            for (int jj = 0; jj < 2; jj++) {
                ldsm4(&bh[4 * jj], smem_u32(&Bh[wn + jj * 16 + br][bc]));
                ldsm4(&bl[4 * jj], smem_u32(&Bl[wn + jj * 16 + br][bc]));
            }

            #pragma unroll
            for (int i = 0; i < 4; i++) {
                #pragma unroll
                for (int j = 0; j < 4; j++) {
                    mma16816(acc[i][j], ah[i], &bh[2 * j]);   // hi*hi
                    mma16816(acc[i][j], ah[i], &bl[2 * j]);   // hi*lo
                    mma16816(acc[i][j], al[i], &bh[2 * j]);   // lo*hi
                }
            }
        }
        __syncthreads();
    }

    // ---- epilogue ----
    const int g  = lane >> 2;
    const int t2 = (lane & 3) * 2;
    #pragma unroll
    for (int i = 0; i < 4; i++) {
        const int m  = m0 + wm + i * 16 + g;
        const float bv0 = bias ? bias[m] : 0.f;
        const float bv1 = bias ? bias[m + 8] : 0.f;
        #pragma unroll
        for (int j = 0; j < 4; j++) {
            const int n = n0 + wn + j * 8 + t2;
            float v0 = acc[i][j][0] * alpha + bv0;
            float v1 = acc[i][j][1] * alpha + bv0;
            float v2 = acc[i][j][2] * alpha + bv1;
            float v3 = acc[i][j][3] * alpha + bv1;
            if (resid) {
                const float* rp = resid + (size_t)bz * sR;
                v0 += rp[(size_t)m * N + n];
                v1 += rp[(size_t)m * N + n + 1];
                v2 += rp[(size_t)(m + 8) * N + n];
                v3 += rp[(size_t)(m + 8) * N + n + 1];
            }
            float2 o0; o0.x = v0; o0.y = v1;
            float2 o1; o1.x = v2; o1.y = v3;
            *(float2*)&C[(size_t)m * N + n] = o0;
            *(float2*)&C[(size_t)(m + 8) * N + n] = o1;
        }
    }
}

// ---------------------------------------------------------------------------
// Row softmax over S[b][q][:], row length 1024. One block per row.
// ---------------------------------------------------------------------------
__global__ __launch_bounds__(256) void softmax_kernel(float* __restrict__ S)
{
    float* p = S + (size_t)blockIdx.x * NPIX;
    const int t = threadIdx.x;

    float v[4];
    float mx = -1e30f;
    #pragma unroll
    for (int i = 0; i < 4; i++) {
        v[i] = p[t + i * 256];
        mx = fmaxf(mx, v[i]);
    }
    __shared__ float red[256];
    red[t] = mx;
    __syncthreads();
    for (int st = 128; st > 0; st >>= 1) {
        if (t < st) red[t] = fmaxf(red[t], red[t + st]);
        __syncthreads();
    }
    mx = red[0];
    __syncthreads();

    float sum = 0.f;
    #pragma unroll
    for (int i = 0; i < 4; i++) {
        v[i] = __expf(v[i] - mx);
        sum += v[i];
    }
    red[t] = sum;
    __syncthreads();
    for (int st = 128; st > 0; st >>= 1) {
        if (t < st) red[t] += red[t + st];
        __syncthreads();
    }
    const float inv = 1.0f / red[0];
    #pragma unroll
    for (int i = 0; i < 4; i++) p[t + i * 256] = v[i] * inv;
}

// ---------------------------------------------------------------------------
// Launch
// ---------------------------------------------------------------------------
extern "C" void kernel_launch(void* const* d_in, const int* in_sizes, int n_in,
                              void* d_out, int out_size)
{
    (void)in_sizes; (void)n_in; (void)out_size;
    const float* x    = (const float*)d_in[0];
    const float* gn_w = (const float*)d_in[1];
    const float* gn_b = (const float*)d_in[2];
    const float* wq   = (const float*)d_in[3];
    const float* bq   = (const float*)d_in[4];
    const float* wk   = (const float*)d_in[5];
    const float* bk   = (const float*)d_in[6];
    const float* wv   = (const float*)d_in[7];
    const float* bv   = (const float*)d_in[8];
    const float* wp   = (const float*)d_in[9];
    const float* bp   = (const float*)d_in[10];
    float* out = (float*)d_out;

    float *H, *Q, *K, *V, *S, *O;
    cudaGetSymbolAddress((void**)&H, g_H);
    cudaGetSymbolAddress((void**)&Q, g_Q);
    cudaGetSymbolAddress((void**)&K, g_K);
    cudaGetSymbolAddress((void**)&V, g_V);
    cudaGetSymbolAddress((void**)&S, g_S);
    cudaGetSymbolAddress((void**)&O, g_O);

    const size_t sCN = (size_t)CH * NPIX;
    const size_t sNN = (size_t)NPIX * NPIX;
    const float scale = 0.044194173824159223f; // 512^-0.5

    // 1) GroupNorm
    groupnorm_kernel<<<BATCH * NG, 256>>>(x, gn_w, gn_b, H);

    // 2) Q/K/V: Y[b][o][n] = W[o][c] H[b][c][n] + bias
    //    A = W [M=512][K=512] direct; B = H [K=512][N=1024] transposed
    {
        dim3 grid(NPIX / 128, CH / 128, BATCH);
        mma_gemm<false, true><<<grid, 256>>>(wq, H, Q, CH, NPIX, CH, CH, NPIX,
                                             0, sCN, sCN, bq, nullptr, 0, 1.f);
        mma_gemm<false, true><<<grid, 256>>>(wk, H, K, CH, NPIX, CH, CH, NPIX,
                                             0, sCN, sCN, bk, nullptr, 0, 1.f);
        mma_gemm<false, true><<<grid, 256>>>(wv, H, V, CH, NPIX, CH, CH, NPIX,
                                             0, sCN, sCN, bv, nullptr, 0, 1.f);
    }

    // 3) S[b][q][k] = scale * sum_c Q[b][c][q] K[b][c][k]
    //    A = Q [K=512][M=1024] transposed; B = K [K=512][N=1024] transposed
    {
        dim3 grid(NPIX / 128, NPIX / 128, BATCH);
        mma_gemm<true, true><<<grid, 256>>>(Q, K, S, NPIX, NPIX, CH, NPIX, NPIX,
                                            sCN, sCN, sNN, nullptr, nullptr, 0, scale);
    }

    // 4) Softmax rows
    softmax_kernel<<<BATCH * NPIX, 256>>>(S);

    // 5) O[b][c][n] = sum_m V[b][c][m] S[b][n][m]
    //    A = V [M=512][K=1024] direct; B = S [N=1024][K=1024] direct
    {
        dim3 grid(NPIX / 128, CH / 128, BATCH);
        mma_gemm<false, false><<<grid, 256>>>(V, S, O, CH, NPIX, NPIX, NPIX, NPIX,
                                              sCN, sNN, sCN, nullptr, nullptr, 0, 1.f);
    }

    // 6) out = x + Wp O + bp
    //    A = Wp direct; B = O [K=512][N=1024] transposed
    {
        dim3 grid(NPIX / 128, CH / 128, BATCH);
        mma_gemm<false, true><<<grid, 256>>>(wp, O, out, CH, NPIX, CH, CH, NPIX,
                                             0, sCN, sCN, bp, x, sCN, 1.f);
    }
}

// round 4
// speedup vs baseline: 2.8972x; 1.1441x over previous
#include <cuda_runtime.h>
#include <cuda_bf16.h>
#include <cstdint>
#include <cstddef>

#define BATCH 32
#define CH    512
#define NPIX  1024
#define NG    32
#define CPG   16
#define EPS   1e-6f

// ---------------------------------------------------------------------------
// Scratch: all intermediates as separate bf16 hi/lo planes, K-contiguous
// for their consumer GEMM.
// ---------------------------------------------------------------------------
#define SZ_CN ((size_t)BATCH * NPIX * CH)    // 16.7M elements
#define SZ_NN ((size_t)BATCH * NPIX * NPIX)  // 33.5M elements

__device__ __nv_bfloat16 g_Hh[SZ_CN], g_Hl[SZ_CN];   // H^T [b][n][c]
__device__ __nv_bfloat16 g_Qh[SZ_CN], g_Ql[SZ_CN];   // Q   [b][n][co]
__device__ __nv_bfloat16 g_Kh[SZ_CN], g_Kl[SZ_CN];   // K   [b][n][co]
__device__ __nv_bfloat16 g_Vh[SZ_CN], g_Vl[SZ_CN];   // V   [b][co][n]
__device__ float         g_S [SZ_NN];                 // logits fp32
__device__ __nv_bfloat16 g_Sp[SZ_NN];                 // probs bf16 (single plane)
__device__ __nv_bfloat16 g_Oh[SZ_CN], g_Ol[SZ_CN];   // O^T [b][q][co]
__device__ __nv_bfloat16 g_Wh[4 * (size_t)CH * CH], g_Wl[4 * (size_t)CH * CH];

// ---------------------------------------------------------------------------
// Helpers
// ---------------------------------------------------------------------------
__device__ __forceinline__ uint32_t smem_u32(const void* p) {
    return (uint32_t)__cvta_generic_to_shared(p);
}
__device__ __forceinline__ void ldsm4(uint32_t r[4], uint32_t a) {
    asm volatile("ldmatrix.sync.aligned.m8n8.x4.shared.b16 {%0,%1,%2,%3}, [%4];"
        : "=r"(r[0]), "=r"(r[1]), "=r"(r[2]), "=r"(r[3]) : "r"(a));
}
__device__ __forceinline__ void mma16816(float d[4], const uint32_t a[4], const uint32_t* b) {
    asm volatile(
        "mma.sync.aligned.m16n8k16.row.col.f32.bf16.bf16.f32 "
        "{%0,%1,%2,%3}, {%4,%5,%6,%7}, {%8,%9}, {%0,%1,%2,%3};"
        : "+f"(d[0]), "+f"(d[1]), "+f"(d[2]), "+f"(d[3])
        : "r"(a[0]), "r"(a[1]), "r"(a[2]), "r"(a[3]), "r"(b[0]), "r"(b[1]));
}
__device__ __forceinline__ void cp16(uint32_t s, const void* g) {
    asm volatile("cp.async.cg.shared.global [%0], [%1], 16;" :: "r"(s), "l"(g));
}
__device__ __forceinline__ void cp_commit() {
    asm volatile("cp.async.commit_group;" ::: "memory");
}
template<int n>
__device__ __forceinline__ void cp_wait() {
    asm volatile("cp.async.wait_group %0;" :: "n"(n) : "memory");
}
__device__ __forceinline__ void splitf(float x, __nv_bfloat16& h, __nv_bfloat16& l) {
    h = __float2bfloat16(x);
    l = __float2bfloat16(x - __bfloat162float(h));
}

// ---------------------------------------------------------------------------
// Weight pack: 4 x [512][512] fp32 -> hi/lo planes
// ---------------------------------------------------------------------------
__global__ __launch_bounds__(256) void pack_w_kernel(
    const float* __restrict__ a0, const float* __restrict__ a1,
    const float* __restrict__ a2, const float* __restrict__ a3,
    __nv_bfloat16* __restrict__ oh, __nv_bfloat16* __restrict__ ol)
{
    int i = blockIdx.x * 256 + threadIdx.x;
    int t = i >> 18;
    int j = i & 262143;
    const float* src = (t == 0) ? a0 : (t == 1) ? a1 : (t == 2) ? a2 : a3;
    __nv_bfloat16 h, l;
    splitf(src[j], h, l);
    oh[i] = h; ol[i] = l;
}

// ---------------------------------------------------------------------------
// GroupNorm -> transposed hi/lo planes H^T[b][n][c]
// ---------------------------------------------------------------------------
__global__ __launch_bounds__(256) void gn_kernel(
    const float* __restrict__ x, const float* __restrict__ w,
    const float* __restrict__ b,
    __nv_bfloat16* __restrict__ Hh, __nv_bfloat16* __restrict__ Hl)
{
    const int bg = blockIdx.x;
    const int batch = bg >> 5;
    const int g = bg & 31;
    const int tid = threadIdx.x;
    const float* xp = x + ((size_t)batch * CH + (size_t)g * CPG) * NPIX;

    float s = 0.f, ss = 0.f;
    for (int i = tid; i < CPG * NPIX; i += 256) {
        float v = xp[i];
        s += v; ss += v * v;
    }
    __shared__ float sh_s[256], sh_ss[256];
    sh_s[tid] = s; sh_ss[tid] = ss;
    __syncthreads();
    for (int st = 128; st > 0; st >>= 1) {
        if (tid < st) { sh_s[tid] += sh_s[tid + st]; sh_ss[tid] += sh_ss[tid + st]; }
        __syncthreads();
    }
    const float mean = sh_s[0] * (1.0f / (CPG * NPIX));
    const float var  = sh_ss[0] * (1.0f / (CPG * NPIX)) - mean * mean;
    const float inv  = rsqrtf(var + EPS);

    __shared__ float st[512][17];

    for (int half = 0; half < 2; half++) {
        for (int i = tid; i < CPG * 512; i += 256) {
            int c16 = i >> 9;
            int nl  = i & 511;
            int c   = g * CPG + c16;
            float v = (xp[c16 * NPIX + half * 512 + nl] - mean) * inv;
            st[nl][c16] = v * w[c] + b[c];
        }
        __syncthreads();
        size_t dst = ((size_t)batch * NPIX + half * 512) * CH + g * CPG;
        for (int i = tid; i < CPG * 512; i += 256) {
            int nl = i >> 4;
            int c16 = i & 15;
            __nv_bfloat16 h, l;
            splitf(st[nl][c16], h, l);
            Hh[dst + (size_t)nl * CH + c16] = h;
            Hl[dst + (size_t)nl * CH + c16] = l;
        }
        __syncthreads();
    }
}

// ---------------------------------------------------------------------------
// Row softmax over fp32 logits -> single bf16 prob plane
// ---------------------------------------------------------------------------
__global__ __launch_bounds__(256) void softmax_kernel(
    const float* __restrict__ S, __nv_bfloat16* __restrict__ Sp)
{
    const float* p = S + (size_t)blockIdx.x * NPIX;
    __nv_bfloat16* po = Sp + (size_t)blockIdx.x * NPIX;
    const int t = threadIdx.x;

    float v[4];
    float mx = -1e30f;
    #pragma unroll
    for (int i = 0; i < 4; i++) { v[i] = p[t + i * 256]; mx = fmaxf(mx, v[i]); }
    __shared__ float red[256];
    red[t] = mx;
    __syncthreads();
    for (int st = 128; st > 0; st >>= 1) {
        if (t < st) red[t] = fmaxf(red[t], red[t + st]);
        __syncthreads();
    }
    mx = red[0];
    __syncthreads();
    float sum = 0.f;
    #pragma unroll
    for (int i = 0; i < 4; i++) { v[i] = __expf(v[i] - mx); sum += v[i]; }
    red[t] = sum;
    __syncthreads();
    for (int st = 128; st > 0; st >>= 1) {
        if (t < st) red[t] += red[t + st];
        __syncthreads();
    }
    const float inv = 1.0f / red[0];
    #pragma unroll
    for (int i = 0; i < 4; i++) po[t + i * 256] = __float2bfloat16(v[i] * inv);
}

// ---------------------------------------------------------------------------
// Tensor-core GEMM over bf16 planes:
//   C[m][n] = alpha * sum_k A(m,k)*B(n,k) + bias_row[m] + bias_col[n] (+resid)
// A: [M][K] bf16 hi(/lo), B: [N][K] bf16 hi/lo, both K-contiguous.
// TERMS=3: ah*bh + ah*bl + al*bh ; TERMS=2: ah*bh + ah*bl (A single plane)
// OUTF32=true: fp32 output; false: bf16 hi/lo plane output.
// Block 128x128, k-chunk 32, 3-stage cp.async pipeline, 8 warps (2m x 4n).
// ---------------------------------------------------------------------------
#define TILE_B   10240            // 128 rows * 40 halves * 2B
#define ROWS_H   40               // padded row stride in halves

template<int TERMS, bool OUTF32>
__global__ __launch_bounds__(256) void mma_gemm(
    const __nv_bfloat16* __restrict__ Ah, const __nv_bfloat16* __restrict__ Al,
    const __nv_bfloat16* __restrict__ Bh, const __nv_bfloat16* __restrict__ Bl,
    void* __restrict__ C0, void* __restrict__ C1,
    int N, int K,
    size_t sA, size_t sB, size_t sC,
    const float* __restrict__ bias_row, const float* __restrict__ bias_col,
    const float* __restrict__ resid, size_t sR, float alpha)
{
    constexpr int AP = (TERMS == 3) ? 2 : 1;
    constexpr int NTILES = AP + 2;
    constexpr int STAGE = NTILES * TILE_B;

    extern __shared__ __align__(1024) char smem[];
    const uint32_t sb = smem_u32(smem);

    const int tid  = threadIdx.x;
    const int lane = tid & 31;
    const int warp = tid >> 5;
    const int wm = (warp >> 2) * 64;
    const int wn = (warp & 3) * 32;
    const int m0 = blockIdx.y * 128;
    const int n0 = blockIdx.x * 128;
    const int bz = blockIdx.z;

    const __nv_bfloat16* gA[2];
    gA[0] = Ah + (size_t)bz * sA;
    gA[1] = (TERMS == 3) ? (Al + (size_t)bz * sA) : nullptr;
    const __nv_bfloat16* gB[2];
    gB[0] = Bh + (size_t)bz * sB;
    gB[1] = Bl + (size_t)bz * sB;

    // per-thread fill coordinates: 512 (row,seg) pairs per tile, 2 per thread
    const int r_a  = tid >> 2;          // wait, need 2 entries; compute inline below

    (void)r_a;
    auto issue = [&](int c) {
        const int stg = c % 3;
        const int k0 = c * 32;
        const uint32_t sbase = sb + stg * STAGE;
        #pragma unroll
        for (int i = 0; i < 2; i++) {
            const int idx = tid + i * 256;       // 0..511
            const int r = idx >> 2;
            const int seg = idx & 3;
            const uint32_t soff = r * (ROWS_H * 2) + seg * 16;
            const size_t ga = (size_t)(m0 + r) * K + k0 + seg * 8;
            const size_t gb = (size_t)(n0 + r) * K + k0 + seg * 8;
            #pragma unroll
            for (int t = 0; t < AP; t++)
                cp16(sbase + t * TILE_B + soff, gA[t] + ga);
            #pragma unroll
            for (int t = 0; t < 2; t++)
                cp16(sbase + (AP + t) * TILE_B + soff, gB[t] + gb);
        }
        cp_commit();
    };

    float acc[4][4][4] = {};

    const int nc = K >> 5;
    issue(0);
    issue(1);

    const int ar = lane & 15;
    const int ac0 = (lane >> 4) * 8;
    const int br = (lane & 7) + (lane >> 4) * 8;
    const int bc0 = ((lane >> 3) & 1) * 8;

    for (int c = 0; c < nc; c++) {
        cp_wait<1>();
        __syncthreads();

        const int stg = c % 3;
        const __nv_bfloat16* TAh = (const __nv_bfloat16*)(smem + stg * STAGE);
        const __nv_bfloat16* TAl = (const __nv_bfloat16*)(smem + stg * STAGE + TILE_B);
        const __nv_bfloat16* TBh = (const __nv_bfloat16*)(smem + stg * STAGE + AP * TILE_B);
        const __nv_bfloat16* TBl = (const __nv_bfloat16*)(smem + stg * STAGE + (AP + 1) * TILE_B);

        #pragma unroll
        for (int kk = 0; kk < 32; kk += 16) {
            uint32_t ah[4][4], al[4][4];
            uint32_t bh[8], bl[8];
            #pragma unroll
            for (int i = 0; i < 4; i++) {
                ldsm4(ah[i], smem_u32(TAh + (wm + i * 16 + ar) * ROWS_H + kk + ac0));
                if (TERMS == 3)
                    ldsm4(al[i], smem_u32(TAl + (wm + i * 16 + ar) * ROWS_H + kk + ac0));
            }
            #pragma unroll
            for (int jj = 0; jj < 2; jj++) {
                ldsm4(&bh[4 * jj], smem_u32(TBh + (wn + jj * 16 + br) * ROWS_H + kk + bc0));
                ldsm4(&bl[4 * jj], smem_u32(TBl + (wn + jj * 16 + br) * ROWS_H + kk + bc0));
            }
            #pragma unroll
            for (int i = 0; i < 4; i++) {
                #pragma unroll
                for (int j = 0; j < 4; j++) {
                    mma16816(acc[i][j], ah[i], &bh[2 * j]);
                    mma16816(acc[i][j], ah[i], &bl[2 * j]);
                    if (TERMS == 3)
                        mma16816(acc[i][j], al[i], &bh[2 * j]);
                }
            }
        }
        if (c + 2 < nc) issue(c + 2);
    }

    // ---- epilogue ----
    const int g  = lane >> 2;
    const int t2 = (lane & 3) * 2;
    #pragma unroll
    for (int i = 0; i < 4; i++) {
        const int m = m0 + wm + i * 16 + g;
        const float br0 = bias_row ? bias_row[m] : 0.f;
        const float br1 = bias_row ? bias_row[m + 8] : 0.f;
        #pragma unroll
        for (int j = 0; j < 4; j++) {
            const int n = n0 + wn + j * 8 + t2;
            float bc0v = 0.f, bc1v = 0.f;
            if (bias_col) { bc0v = bias_col[n]; bc1v = bias_col[n + 1]; }
            float v0 = acc[i][j][0] * alpha + br0 + bc0v;
            float v1 = acc[i][j][1] * alpha + br0 + bc1v;
            float v2 = acc[i][j][2] * alpha + br1 + bc0v;
            float v3 = acc[i][j][3] * alpha + br1 + bc1v;
            if (resid) {
                const float* rp = resid + (size_t)bz * sR;
                v0 += rp[(size_t)m * N + n];
                v1 += rp[(size_t)m * N + n + 1];
                v2 += rp[(size_t)(m + 8) * N + n];
                v3 += rp[(size_t)(m + 8) * N + n + 1];
            }
            if (OUTF32) {
                float* C = (float*)C0 + (size_t)bz * sC;
                float2 o0; o0.x = v0; o0.y = v1;
                float2 o1; o1.x = v2; o1.y = v3;
                *(float2*)&C[(size_t)m * N + n] = o0;
                *(float2*)&C[(size_t)(m + 8) * N + n] = o1;
            } else {
                __nv_bfloat16* Ch = (__nv_bfloat16*)C0 + (size_t)bz * sC;
                __nv_bfloat16* Cl = (__nv_bfloat16*)C1 + (size_t)bz * sC;
                __nv_bfloat16 h0, l0, h1, l1, h2, l2, h3, l3;
                splitf(v0, h0, l0); splitf(v1, h1, l1);
                splitf(v2, h2, l2); splitf(v3, h3, l3);
                __nv_bfloat162 hh01; hh01.x = h0; hh01.y = h1;
                __nv_bfloat162 ll01; ll01.x = l0; ll01.y = l1;
                __nv_bfloat162 hh23; hh23.x = h2; hh23.y = h3;
                __nv_bfloat162 ll23; ll23.x = l2; ll23.y = l3;
                *(__nv_bfloat162*)&Ch[(size_t)m * N + n] = hh01;
                *(__nv_bfloat162*)&Cl[(size_t)m * N + n] = ll01;
                *(__nv_bfloat162*)&Ch[(size_t)(m + 8) * N + n] = hh23;
                *(__nv_bfloat162*)&Cl[(size_t)(m + 8) * N + n] = ll23;
            }
        }
    }
}

// ---------------------------------------------------------------------------
// Launch
// ---------------------------------------------------------------------------
extern "C" void kernel_launch(void* const* d_in, const int* in_sizes, int n_in,
                              void* d_out, int out_size)
{
    (void)in_sizes; (void)n_in; (void)out_size;
    const float* x    = (const float*)d_in[0];
    const float* gn_w = (const float*)d_in[1];
    const float* gn_b = (const float*)d_in[2];
    const float* wq   = (const float*)d_in[3];
    const float* bq   = (const float*)d_in[4];
    const float* wk   = (const float*)d_in[5];
    const float* bk   = (const float*)d_in[6];
    const float* wv   = (const float*)d_in[7];
    const float* bv   = (const float*)d_in[8];
    const float* wp   = (const float*)d_in[9];
    const float* bp   = (const float*)d_in[10];
    float* out = (float*)d_out;

    __nv_bfloat16 *Hh, *Hl, *Qh, *Ql, *Kh, *Kl, *Vh, *Vl, *Oh, *Ol, *Wh, *Wl, *Sp;
    float* S;
    cudaGetSymbolAddress((void**)&Hh, g_Hh); cudaGetSymbolAddress((void**)&Hl, g_Hl);
    cudaGetSymbolAddress((void**)&Qh, g_Qh); cudaGetSymbolAddress((void**)&Ql, g_Ql);
    cudaGetSymbolAddress((void**)&Kh, g_Kh); cudaGetSymbolAddress((void**)&Kl, g_Kl);
    cudaGetSymbolAddress((void**)&Vh, g_Vh); cudaGetSymbolAddress((void**)&Vl, g_Vl);
    cudaGetSymbolAddress((void**)&Oh, g_Oh); cudaGetSymbolAddress((void**)&Ol, g_Ol);
    cudaGetSymbolAddress((void**)&Wh, g_Wh); cudaGetSymbolAddress((void**)&Wl, g_Wl);
    cudaGetSymbolAddress((void**)&S,  g_S);  cudaGetSymbolAddress((void**)&Sp, g_Sp);

    const int SM3 = 3 * 4 * TILE_B;  // 122880
    const int SM2 = 3 * 3 * TILE_B;  // 92160
    static bool attr_done = false;
    if (!attr_done) {
        cudaFuncSetAttribute(mma_gemm<3, true>,  cudaFuncAttributeMaxDynamicSharedMemorySize, SM3);
        cudaFuncSetAttribute(mma_gemm<3, false>, cudaFuncAttributeMaxDynamicSharedMemorySize, SM3);
        cudaFuncSetAttribute(mma_gemm<2, false>, cudaFuncAttributeMaxDynamicSharedMemorySize, SM2);
        attr_done = true;
    }

    const size_t WSZ = (size_t)CH * CH;
    const size_t sCN = (size_t)CH * NPIX;
    const size_t sNN = (size_t)NPIX * NPIX;
    const float scale = 0.044194173824159223f; // 512^-0.5

    // 0) pack weights into hi/lo planes
    pack_w_kernel<<<4096, 256>>>(wq, wk, wv, wp, Wh, Wl);

    // 1) GroupNorm -> H^T planes [b][n][c]
    gn_kernel<<<BATCH * NG, 256>>>(x, gn_w, gn_b, Hh, Hl);

    // 2) Q[n][co] = H^T[n][c] . Wq[co][c] + bq  (M=1024,N=512,K=512)
    {
        dim3 grid(CH / 128, NPIX / 128, BATCH);
        mma_gemm<3, false><<<grid, 256, SM3>>>(Hh, Hl, Wh, Wl, Qh, Ql,
            CH, CH, sCN, 0, sCN, nullptr, bq, nullptr, 0, 1.f);
        mma_gemm<3, false><<<grid, 256, SM3>>>(Hh, Hl, Wh + WSZ, Wl + WSZ, Kh, Kl,
            CH, CH, sCN, 0, sCN, nullptr, bk, nullptr, 0, 1.f);
    }
    // 3) V[co][n] = Wv[co][c] . H^T[n][c] + bv  (M=512,N=1024,K=512)
    {
        dim3 grid(NPIX / 128, CH / 128, BATCH);
        mma_gemm<3, false><<<grid, 256, SM3>>>(Wh + 2 * WSZ, Wl + 2 * WSZ, Hh, Hl, Vh, Vl,
            NPIX, CH, 0, sCN, sCN, bv, nullptr, nullptr, 0, 1.f);
    }
    // 4) S[q][k] = scale * Q[q][c] . K[k][c]  (M=N=1024,K=512) fp32
    {
        dim3 grid(NPIX / 128, NPIX / 128, BATCH);
        mma_gemm<3, true><<<grid, 256, SM3>>>(Qh, Ql, Kh, Kl, S, nullptr,
            NPIX, CH, sCN, sCN, sNN, nullptr, nullptr, nullptr, 0, scale);
    }
    // 5) softmax -> bf16 probs
    softmax_kernel<<<BATCH * NPIX, 256>>>(S, Sp);

    // 6) O^T[q][co] = P[q][k] . V[co][k]  (M=1024,N=512,K=1024), 2-term
    {
        dim3 grid(CH / 128, NPIX / 128, BATCH);
        mma_gemm<2, false><<<grid, 256, SM2>>>(Sp, nullptr, Vh, Vl, Oh, Ol,
            CH, NPIX, sNN, sCN, sCN, nullptr, nullptr, nullptr, 0, 1.f);
    }
    // 7) out[co][n] = Wp[co][c] . O^T[n][c] + bp + x  (M=512,N=1024,K=512)
    {
        dim3 grid(NPIX / 128, CH / 128, BATCH);
        mma_gemm<3, true><<<grid, 256, SM3>>>(Wh + 3 * WSZ, Wl + 3 * WSZ, Oh, Ol, out, nullptr,
            NPIX, CH, 0, sCN, sCN, bp, nullptr, x, sCN, 1.f);
    }
}

// round 5
// speedup vs baseline: 3.2497x; 1.1217x over previous
#include <cuda_runtime.h>
#include <cuda_bf16.h>
#include <cstdint>
#include <cstddef>

#define BATCH 32
#define CH    512
#define NPIX  1024
#define NG    32
#define CPG   16
#define EPS   1e-6f

// ---------------------------------------------------------------------------
// Scratch: all intermediates as separate bf16 hi/lo planes, K-contiguous
// for their consumer GEMM.
// ---------------------------------------------------------------------------
#define SZ_CN ((size_t)BATCH * NPIX * CH)    // 16.7M elements
#define SZ_NN ((size_t)BATCH * NPIX * NPIX)  // 33.5M elements

__device__ __nv_bfloat16 g_Hh[SZ_CN], g_Hl[SZ_CN];   // H^T [b][n][c]
__device__ __nv_bfloat16 g_Qh[SZ_CN], g_Ql[SZ_CN];   // Q   [b][n][co]
__device__ __nv_bfloat16 g_Kh[SZ_CN], g_Kl[SZ_CN];   // K   [b][n][co]
__device__ __nv_bfloat16 g_Vh[SZ_CN], g_Vl[SZ_CN];   // V   [b][co][n]
__device__ float         g_S [SZ_NN];                 // logits fp32
__device__ __nv_bfloat16 g_Sp[SZ_NN];                 // probs bf16 (single plane)
__device__ __nv_bfloat16 g_Oh[SZ_CN], g_Ol[SZ_CN];   // O^T [b][q][co]
__device__ __nv_bfloat16 g_Wh[4 * (size_t)CH * CH], g_Wl[4 * (size_t)CH * CH];

// ---------------------------------------------------------------------------
// Helpers
// ---------------------------------------------------------------------------
__device__ __forceinline__ uint32_t smem_u32(const void* p) {
    return (uint32_t)__cvta_generic_to_shared(p);
}
__device__ __forceinline__ void ldsm4(uint32_t r[4], uint32_t a) {
    asm volatile("ldmatrix.sync.aligned.m8n8.x4.shared.b16 {%0,%1,%2,%3}, [%4];"
        : "=r"(r[0]), "=r"(r[1]), "=r"(r[2]), "=r"(r[3]) : "r"(a));
}
__device__ __forceinline__ void mma16816(float d[4], const uint32_t a[4], const uint32_t* b) {
    asm volatile(
        "mma.sync.aligned.m16n8k16.row.col.f32.bf16.bf16.f32 "
        "{%0,%1,%2,%3}, {%4,%5,%6,%7}, {%8,%9}, {%0,%1,%2,%3};"
        : "+f"(d[0]), "+f"(d[1]), "+f"(d[2]), "+f"(d[3])
        : "r"(a[0]), "r"(a[1]), "r"(a[2]), "r"(a[3]), "r"(b[0]), "r"(b[1]));
}
__device__ __forceinline__ void cp16(uint32_t s, const void* g) {
    asm volatile("cp.async.cg.shared.global [%0], [%1], 16;" :: "r"(s), "l"(g));
}
__device__ __forceinline__ void cp_commit() {
    asm volatile("cp.async.commit_group;" ::: "memory");
}
template<int n>
__device__ __forceinline__ void cp_wait() {
    asm volatile("cp.async.wait_group %0;" :: "n"(n) : "memory");
}
__device__ __forceinline__ void splitf(float x, __nv_bfloat16& h, __nv_bfloat16& l) {
    h = __float2bfloat16(x);
    l = __float2bfloat16(x - __bfloat162float(h));
}

// ---------------------------------------------------------------------------
// Weight pack: 4 x [512][512] fp32 -> hi/lo planes
// ---------------------------------------------------------------------------
__global__ __launch_bounds__(256) void pack_w_kernel(
    const float* __restrict__ a0, const float* __restrict__ a1,
    const float* __restrict__ a2, const float* __restrict__ a3,
    __nv_bfloat16* __restrict__ oh, __nv_bfloat16* __restrict__ ol)
{
    int i = blockIdx.x * 256 + threadIdx.x;
    int t = i >> 18;
    int j = i & 262143;
    const float* src = (t == 0) ? a0 : (t == 1) ? a1 : (t == 2) ? a2 : a3;
    __nv_bfloat16 h, l;
    splitf(src[j], h, l);
    oh[i] = h; ol[i] = l;
}

// ---------------------------------------------------------------------------
// GroupNorm -> transposed hi/lo planes H^T[b][n][c]
// ---------------------------------------------------------------------------
__global__ __launch_bounds__(256) void gn_kernel(
    const float* __restrict__ x, const float* __restrict__ w,
    const float* __restrict__ b,
    __nv_bfloat16* __restrict__ Hh, __nv_bfloat16* __restrict__ Hl)
{
    const int bg = blockIdx.x;
    const int batch = bg >> 5;
    const int g = bg & 31;
    const int tid = threadIdx.x;
    const float* xp = x + ((size_t)batch * CH + (size_t)g * CPG) * NPIX;

    float s = 0.f, ss = 0.f;
    for (int i = tid; i < CPG * NPIX; i += 256) {
        float v = xp[i];
        s += v; ss += v * v;
    }
    __shared__ float sh_s[256], sh_ss[256];
    sh_s[tid] = s; sh_ss[tid] = ss;
    __syncthreads();
    for (int st = 128; st > 0; st >>= 1) {
        if (tid < st) { sh_s[tid] += sh_s[tid + st]; sh_ss[tid] += sh_ss[tid + st]; }
        __syncthreads();
    }
    const float mean = sh_s[0] * (1.0f / (CPG * NPIX));
    const float var  = sh_ss[0] * (1.0f / (CPG * NPIX)) - mean * mean;
    const float inv  = rsqrtf(var + EPS);

    __shared__ float st[512][17];

    for (int half = 0; half < 2; half++) {
        for (int i = tid; i < CPG * 512; i += 256) {
            int c16 = i >> 9;
            int nl  = i & 511;
            int c   = g * CPG + c16;
            float v = (xp[c16 * NPIX + half * 512 + nl] - mean) * inv;
            st[nl][c16] = v * w[c] + b[c];
        }
        __syncthreads();
        size_t dst = ((size_t)batch * NPIX + half * 512) * CH + g * CPG;
        for (int i = tid; i < CPG * 512; i += 256) {
            int nl = i >> 4;
            int c16 = i & 15;
            __nv_bfloat16 h, l;
            splitf(st[nl][c16], h, l);
            Hh[dst + (size_t)nl * CH + c16] = h;
            Hl[dst + (size_t)nl * CH + c16] = l;
        }
        __syncthreads();
    }
}

// ---------------------------------------------------------------------------
// Row softmax over fp32 logits -> single bf16 prob plane
// ---------------------------------------------------------------------------
__global__ __launch_bounds__(256) void softmax_kernel(
    const float* __restrict__ S, __nv_bfloat16* __restrict__ Sp)
{
    const float* p = S + (size_t)blockIdx.x * NPIX;
    __nv_bfloat16* po = Sp + (size_t)blockIdx.x * NPIX;
    const int t = threadIdx.x;

    float v[4];
    float mx = -1e30f;
    #pragma unroll
    for (int i = 0; i < 4; i++) { v[i] = p[t + i * 256]; mx = fmaxf(mx, v[i]); }
    __shared__ float red[256];
    red[t] = mx;
    __syncthreads();
    for (int st = 128; st > 0; st >>= 1) {
        if (t < st) red[t] = fmaxf(red[t], red[t + st]);
        __syncthreads();
    }
    mx = red[0];
    __syncthreads();
    float sum = 0.f;
    #pragma unroll
    for (int i = 0; i < 4; i++) { v[i] = __expf(v[i] - mx); sum += v[i]; }
    red[t] = sum;
    __syncthreads();
    for (int st = 128; st > 0; st >>= 1) {
        if (t < st) red[t] += red[t + st];
        __syncthreads();
    }
    const float inv = 1.0f / red[0];
    #pragma unroll
    for (int i = 0; i < 4; i++) po[t + i * 256] = __float2bfloat16(v[i] * inv);
}

// ---------------------------------------------------------------------------
// Tensor-core GEMM over bf16 planes:
//   C[m][n] = alpha * sum_k A(m,k)*B(n,k) + bias_row[m] + bias_col[n] (+resid)
// A: [M][K] bf16 hi(/lo), B: [N][K] bf16 hi/lo, both K-contiguous.
// TERMS=3: ah*bh + ah*bl + al*bh ; TERMS=2: ah*bh + ah*bl (A single plane)
// OUTF32=true: fp32 output; false: bf16 hi/lo plane output.
// Block 128x128, k-chunk 32, 2-stage cp.async double buffer, 8 warps.
// __launch_bounds__(256,2): 2 CTAs/SM (smem <= 81.9KB, regs <= 128).
// ---------------------------------------------------------------------------
#define TILE_B   10240            // 128 rows * 40 halves * 2B
#define ROWS_H   40               // padded row stride in halves

template<int TERMS, bool OUTF32>
__global__ __launch_bounds__(256, 2) void mma_gemm(
    const __nv_bfloat16* __restrict__ Ah, const __nv_bfloat16* __restrict__ Al,
    const __nv_bfloat16* __restrict__ Bh, const __nv_bfloat16* __restrict__ Bl,
    void* __restrict__ C0, void* __restrict__ C1,
    int N, int K,
    size_t sA, size_t sB, size_t sC,
    const float* __restrict__ bias_row, const float* __restrict__ bias_col,
    const float* __restrict__ resid, size_t sR, float alpha)
{
    constexpr int AP = (TERMS == 3) ? 2 : 1;
    constexpr int NTILES = AP + 2;
    constexpr int STAGE = NTILES * TILE_B;

    extern __shared__ __align__(1024) char smem[];
    const uint32_t sb = smem_u32(smem);

    const int tid  = threadIdx.x;
    const int lane = tid & 31;
    const int warp = tid >> 5;
    const int wm = (warp >> 2) * 64;
    const int wn = (warp & 3) * 32;
    const int m0 = blockIdx.y * 128;
    const int n0 = blockIdx.x * 128;
    const int bz = blockIdx.z;

    const __nv_bfloat16* gA[2];
    gA[0] = Ah + (size_t)bz * sA;
    gA[1] = (TERMS == 3) ? (Al + (size_t)bz * sA) : nullptr;
    const __nv_bfloat16* gB[2];
    gB[0] = Bh + (size_t)bz * sB;
    gB[1] = Bl + (size_t)bz * sB;

    auto issue = [&](int c) {
        const int stg = c & 1;
        const int k0 = c * 32;
        const uint32_t sbase = sb + stg * STAGE;
        #pragma unroll
        for (int i = 0; i < 2; i++) {
            const int idx = tid + i * 256;       // 0..511
            const int r = idx >> 2;
            const int seg = idx & 3;
            const uint32_t soff = r * (ROWS_H * 2) + seg * 16;
            const size_t ga = (size_t)(m0 + r) * K + k0 + seg * 8;
            const size_t gb = (size_t)(n0 + r) * K + k0 + seg * 8;
            #pragma unroll
            for (int t = 0; t < AP; t++)
                cp16(sbase + t * TILE_B + soff, gA[t] + ga);
            #pragma unroll
            for (int t = 0; t < 2; t++)
                cp16(sbase + (AP + t) * TILE_B + soff, gB[t] + gb);
        }
        cp_commit();
    };

    float acc[4][4][4] = {};

    const int nc = K >> 5;
    issue(0);

    const int ar = lane & 15;
    const int ac0 = (lane >> 4) * 8;
    const int br = (lane & 7) + (lane >> 4) * 8;
    const int bc0 = ((lane >> 3) & 1) * 8;

    for (int c = 0; c < nc; c++) {
        cp_wait<0>();
        __syncthreads();
        if (c + 1 < nc) issue(c + 1);

        const int stg = c & 1;
        const __nv_bfloat16* TAh = (const __nv_bfloat16*)(smem + stg * STAGE);
        const __nv_bfloat16* TAl = (const __nv_bfloat16*)(smem + stg * STAGE + TILE_B);
        const __nv_bfloat16* TBh = (const __nv_bfloat16*)(smem + stg * STAGE + AP * TILE_B);
        const __nv_bfloat16* TBl = (const __nv_bfloat16*)(smem + stg * STAGE + (AP + 1) * TILE_B);

        #pragma unroll
        for (int kk = 0; kk < 32; kk += 16) {
            uint32_t ah[4][4], al[4][4];
            uint32_t bh[8], bl[8];
            #pragma unroll
            for (int i = 0; i < 4; i++) {
                ldsm4(ah[i], smem_u32(TAh + (wm + i * 16 + ar) * ROWS_H + kk + ac0));
                if (TERMS == 3)
                    ldsm4(al[i], smem_u32(TAl + (wm + i * 16 + ar) * ROWS_H + kk + ac0));
            }
            #pragma unroll
            for (int jj = 0; jj < 2; jj++) {
                ldsm4(&bh[4 * jj], smem_u32(TBh + (wn + jj * 16 + br) * ROWS_H + kk + bc0));
                ldsm4(&bl[4 * jj], smem_u32(TBl + (wn + jj * 16 + br) * ROWS_H + kk + bc0));
            }
            #pragma unroll
            for (int i = 0; i < 4; i++) {
                #pragma unroll
                for (int j = 0; j < 4; j++) {
                    mma16816(acc[i][j], ah[i], &bh[2 * j]);
                    mma16816(acc[i][j], ah[i], &bl[2 * j]);
                    if (TERMS == 3)
                        mma16816(acc[i][j], al[i], &bh[2 * j]);
                }
            }
        }
        // note: next-iteration sync guarantees smem reuse safety
        __syncthreads();
    }

    // ---- epilogue ----
    const int g  = lane >> 2;
    const int t2 = (lane & 3) * 2;
    #pragma unroll
    for (int i = 0; i < 4; i++) {
        const int m = m0 + wm + i * 16 + g;
        const float br0 = bias_row ? bias_row[m] : 0.f;
        const float br1 = bias_row ? bias_row[m + 8] : 0.f;
        #pragma unroll
        for (int j = 0; j < 4; j++) {
            const int n = n0 + wn + j * 8 + t2;
            float bc0v = 0.f, bc1v = 0.f;
            if (bias_col) { bc0v = bias_col[n]; bc1v = bias_col[n + 1]; }
            float v0 = acc[i][j][0] * alpha + br0 + bc0v;
            float v1 = acc[i][j][1] * alpha + br0 + bc1v;
            float v2 = acc[i][j][2] * alpha + br1 + bc0v;
            float v3 = acc[i][j][3] * alpha + br1 + bc1v;
            if (resid) {
                const float* rp = resid + (size_t)bz * sR;
                v0 += rp[(size_t)m * N + n];
                v1 += rp[(size_t)m * N + n + 1];
                v2 += rp[(size_t)(m + 8) * N + n];
                v3 += rp[(size_t)(m + 8) * N + n + 1];
            }
            if (OUTF32) {
                float* C = (float*)C0 + (size_t)bz * sC;
                float2 o0; o0.x = v0; o0.y = v1;
                float2 o1; o1.x = v2; o1.y = v3;
                *(float2*)&C[(size_t)m * N + n] = o0;
                *(float2*)&C[(size_t)(m + 8) * N + n] = o1;
            } else {
                __nv_bfloat16* Ch = (__nv_bfloat16*)C0 + (size_t)bz * sC;
                __nv_bfloat16* Cl = (__nv_bfloat16*)C1 + (size_t)bz * sC;
                __nv_bfloat16 h0, l0, h1, l1, h2, l2, h3, l3;
                splitf(v0, h0, l0); splitf(v1, h1, l1);
                splitf(v2, h2, l2); splitf(v3, h3, l3);
                __nv_bfloat162 hh01; hh01.x = h0; hh01.y = h1;
                __nv_bfloat162 ll01; ll01.x = l0; ll01.y = l1;
                __nv_bfloat162 hh23; hh23.x = h2; hh23.y = h3;
                __nv_bfloat162 ll23; ll23.x = l2; ll23.y = l3;
                *(__nv_bfloat162*)&Ch[(size_t)m * N + n] = hh01;
                *(__nv_bfloat162*)&Cl[(size_t)m * N + n] = ll01;
                *(__nv_bfloat162*)&Ch[(size_t)(m + 8) * N + n] = hh23;
                *(__nv_bfloat162*)&Cl[(size_t)(m + 8) * N + n] = ll23;
            }
        }
    }
}

// ---------------------------------------------------------------------------
// Launch
// ---------------------------------------------------------------------------
extern "C" void kernel_launch(void* const* d_in, const int* in_sizes, int n_in,
                              void* d_out, int out_size)
{
    (void)in_sizes; (void)n_in; (void)out_size;
    const float* x    = (const float*)d_in[0];
    const float* gn_w = (const float*)d_in[1];
    const float* gn_b = (const float*)d_in[2];
    const float* wq   = (const float*)d_in[3];
    const float* bq   = (const float*)d_in[4];
    const float* wk   = (const float*)d_in[5];
    const float* bk   = (const float*)d_in[6];
    const float* wv   = (const float*)d_in[7];
    const float* bv   = (const float*)d_in[8];
    const float* wp   = (const float*)d_in[9];
    const float* bp   = (const float*)d_in[10];
    float* out = (float*)d_out;

    __nv_bfloat16 *Hh, *Hl, *Qh, *Ql, *Kh, *Kl, *Vh, *Vl, *Oh, *Ol, *Wh, *Wl, *Sp;
    float* S;
    cudaGetSymbolAddress((void**)&Hh, g_Hh); cudaGetSymbolAddress((void**)&Hl, g_Hl);
    cudaGetSymbolAddress((void**)&Qh, g_Qh); cudaGetSymbolAddress((void**)&Ql, g_Ql);
    cudaGetSymbolAddress((void**)&Kh, g_Kh); cudaGetSymbolAddress((void**)&Kl, g_Kl);
    cudaGetSymbolAddress((void**)&Vh, g_Vh); cudaGetSymbolAddress((void**)&Vl, g_Vl);
    cudaGetSymbolAddress((void**)&Oh, g_Oh); cudaGetSymbolAddress((void**)&Ol, g_Ol);
    cudaGetSymbolAddress((void**)&Wh, g_Wh); cudaGetSymbolAddress((void**)&Wl, g_Wl);
    cudaGetSymbolAddress((void**)&S,  g_S);  cudaGetSymbolAddress((void**)&Sp, g_Sp);

    const int SM3 = 2 * 4 * TILE_B;  // 81920
    const int SM2 = 2 * 3 * TILE_B;  // 61440
    static bool attr_done = false;
    if (!attr_done) {
        cudaFuncSetAttribute(mma_gemm<3, true>,  cudaFuncAttributeMaxDynamicSharedMemorySize, SM3);
        cudaFuncSetAttribute(mma_gemm<3, false>, cudaFuncAttributeMaxDynamicSharedMemorySize, SM3);
        cudaFuncSetAttribute(mma_gemm<2, false>, cudaFuncAttributeMaxDynamicSharedMemorySize, SM2);
        attr_done = true;
    }

    const size_t WSZ = (size_t)CH * CH;
    const size_t sCN = (size_t)CH * NPIX;
    const size_t sNN = (size_t)NPIX * NPIX;
    const float scale = 0.044194173824159223f; // 512^-0.5

    // 0) pack weights into hi/lo planes
    pack_w_kernel<<<4096, 256>>>(wq, wk, wv, wp, Wh, Wl);

    // 1) GroupNorm -> H^T planes [b][n][c]
    gn_kernel<<<BATCH * NG, 256>>>(x, gn_w, gn_b, Hh, Hl);

    // 2) Q[n][co] = H^T[n][c] . Wq[co][c] + bq  (M=1024,N=512,K=512)
    {
        dim3 grid(CH / 128, NPIX / 128, BATCH);
        mma_gemm<3, false><<<grid, 256, SM3>>>(Hh, Hl, Wh, Wl, Qh, Ql,
            CH, CH, sCN, 0, sCN, nullptr, bq, nullptr, 0, 1.f);
        mma_gemm<3, false><<<grid, 256, SM3>>>(Hh, Hl, Wh + WSZ, Wl + WSZ, Kh, Kl,
            CH, CH, sCN, 0, sCN, nullptr, bk, nullptr, 0, 1.f);
    }
    // 3) V[co][n] = Wv[co][c] . H^T[n][c] + bv  (M=512,N=1024,K=512)
    {
        dim3 grid(NPIX / 128, CH / 128, BATCH);
        mma_gemm<3, false><<<grid, 256, SM3>>>(Wh + 2 * WSZ, Wl + 2 * WSZ, Hh, Hl, Vh, Vl,
            NPIX, CH, 0, sCN, sCN, bv, nullptr, nullptr, 0, 1.f);
    }
    // 4) S[q][k] = scale * Q[q][c] . K[k][c]  (M=N=1024,K=512) fp32
    {
        dim3 grid(NPIX / 128, NPIX / 128, BATCH);
        mma_gemm<3, true><<<grid, 256, SM3>>>(Qh, Ql, Kh, Kl, S, nullptr,
            NPIX, CH, sCN, sCN, sNN, nullptr, nullptr, nullptr, 0, scale);
    }
    // 5) softmax -> bf16 probs
    softmax_kernel<<<BATCH * NPIX, 256>>>(S, Sp);

    // 6) O^T[q][co] = P[q][k] . V[co][k]  (M=1024,N=512,K=1024), 2-term
    {
        dim3 grid(CH / 128, NPIX / 128, BATCH);
        mma_gemm<2, false><<<grid, 256, SM2>>>(Sp, nullptr, Vh, Vl, Oh, Ol,
            CH, NPIX, sNN, sCN, sCN, nullptr, nullptr, nullptr, 0, 1.f);
    }
    // 7) out[co][n] = Wp[co][c] . O^T[n][c] + bp + x  (M=512,N=1024,K=512)
    {
        dim3 grid(NPIX / 128, CH / 128, BATCH);
        mma_gemm<3, true><<<grid, 256, SM3>>>(Wh + 3 * WSZ, Wl + 3 * WSZ, Oh, Ol, out, nullptr,
            NPIX, CH, 0, sCN, sCN, bp, nullptr, x, sCN, 1.f);
    }
}

// round 6
// speedup vs baseline: 3.2899x; 1.0124x over previous
#include <cuda_runtime.h>
#include <cuda_bf16.h>
#include <cstdint>
#include <cstddef>

#define BATCH 32
#define CH    512
#define NPIX  1024
#define NG    32
#define CPG   16
#define EPS   1e-6f

// ---------------------------------------------------------------------------
// Scratch: all intermediates as separate bf16 hi/lo planes, K-contiguous
// for their consumer GEMM.
// ---------------------------------------------------------------------------
#define SZ_CN ((size_t)BATCH * NPIX * CH)    // 16.7M elements
#define SZ_NN ((size_t)BATCH * NPIX * NPIX)  // 33.5M elements

__device__ __nv_bfloat16 g_Hh[SZ_CN], g_Hl[SZ_CN];   // H^T [b][n][c]
__device__ __nv_bfloat16 g_Qh[SZ_CN], g_Ql[SZ_CN];   // Q   [b][n][co]
__device__ __nv_bfloat16 g_Kh[SZ_CN], g_Kl[SZ_CN];   // K   [b][n][co]
__device__ __nv_bfloat16 g_Vh[SZ_CN], g_Vl[SZ_CN];   // V   [b][co][n]
__device__ float         g_S [SZ_NN];                 // logits fp32
__device__ __nv_bfloat16 g_Sp[SZ_NN];                 // probs bf16 (single plane)
__device__ __nv_bfloat16 g_Oh[SZ_CN], g_Ol[SZ_CN];   // O^T [b][q][co]
__device__ __nv_bfloat16 g_Wh[4 * (size_t)CH * CH], g_Wl[4 * (size_t)CH * CH];

// ---------------------------------------------------------------------------
// Helpers
// ---------------------------------------------------------------------------
__device__ __forceinline__ uint32_t smem_u32(const void* p) {
    return (uint32_t)__cvta_generic_to_shared(p);
}
__device__ __forceinline__ void ldsm4(uint32_t r[4], uint32_t a) {
    asm volatile("ldmatrix.sync.aligned.m8n8.x4.shared.b16 {%0,%1,%2,%3}, [%4];"
        : "=r"(r[0]), "=r"(r[1]), "=r"(r[2]), "=r"(r[3]) : "r"(a));
}
__device__ __forceinline__ void mma16816(float d[4], const uint32_t a[4], const uint32_t* b) {
    asm volatile(
        "mma.sync.aligned.m16n8k16.row.col.f32.bf16.bf16.f32 "
        "{%0,%1,%2,%3}, {%4,%5,%6,%7}, {%8,%9}, {%0,%1,%2,%3};"
        : "+f"(d[0]), "+f"(d[1]), "+f"(d[2]), "+f"(d[3])
        : "r"(a[0]), "r"(a[1]), "r"(a[2]), "r"(a[3]), "r"(b[0]), "r"(b[1]));
}
__device__ __forceinline__ void cp16(uint32_t s, const void* g) {
    asm volatile("cp.async.cg.shared.global [%0], [%1], 16;" :: "r"(s), "l"(g));
}
__device__ __forceinline__ void cp_commit() {
    asm volatile("cp.async.commit_group;" ::: "memory");
}
template<int n>
__device__ __forceinline__ void cp_wait() {
    asm volatile("cp.async.wait_group %0;" :: "n"(n) : "memory");
}
__device__ __forceinline__ void splitf(float x, __nv_bfloat16& h, __nv_bfloat16& l) {
    h = __float2bfloat16(x);
    l = __float2bfloat16(x - __bfloat162float(h));
}

// ---------------------------------------------------------------------------
// Weight pack: 4 x [512][512] fp32 -> hi/lo planes
// ---------------------------------------------------------------------------
__global__ __launch_bounds__(256) void pack_w_kernel(
    const float* __restrict__ a0, const float* __restrict__ a1,
    const float* __restrict__ a2, const float* __restrict__ a3,
    __nv_bfloat16* __restrict__ oh, __nv_bfloat16* __restrict__ ol)
{
    int i = blockIdx.x * 256 + threadIdx.x;
    int t = i >> 18;
    int j = i & 262143;
    const float* src = (t == 0) ? a0 : (t == 1) ? a1 : (t == 2) ? a2 : a3;
    __nv_bfloat16 h, l;
    splitf(src[j], h, l);
    oh[i] = h; ol[i] = l;
}

// ---------------------------------------------------------------------------
// GroupNorm -> transposed hi/lo planes H^T[b][n][c]
// ---------------------------------------------------------------------------
__global__ __launch_bounds__(256) void gn_kernel(
    const float* __restrict__ x, const float* __restrict__ w,
    const float* __restrict__ b,
    __nv_bfloat16* __restrict__ Hh, __nv_bfloat16* __restrict__ Hl)
{
    const int bg = blockIdx.x;
    const int batch = bg >> 5;
    const int g = bg & 31;
    const int tid = threadIdx.x;
    const float* xp = x + ((size_t)batch * CH + (size_t)g * CPG) * NPIX;

    float s = 0.f, ss = 0.f;
    for (int i = tid; i < CPG * NPIX; i += 256) {
        float v = xp[i];
        s += v; ss += v * v;
    }
    __shared__ float sh_s[256], sh_ss[256];
    sh_s[tid] = s; sh_ss[tid] = ss;
    __syncthreads();
    for (int st = 128; st > 0; st >>= 1) {
        if (tid < st) { sh_s[tid] += sh_s[tid + st]; sh_ss[tid] += sh_ss[tid + st]; }
        __syncthreads();
    }
    const float mean = sh_s[0] * (1.0f / (CPG * NPIX));
    const float var  = sh_ss[0] * (1.0f / (CPG * NPIX)) - mean * mean;
    const float inv  = rsqrtf(var + EPS);

    __shared__ float st[512][17];

    for (int half = 0; half < 2; half++) {
        for (int i = tid; i < CPG * 512; i += 256) {
            int c16 = i >> 9;
            int nl  = i & 511;
            int c   = g * CPG + c16;
            float v = (xp[c16 * NPIX + half * 512 + nl] - mean) * inv;
            st[nl][c16] = v * w[c] + b[c];
        }
        __syncthreads();
        size_t dst = ((size_t)batch * NPIX + half * 512) * CH + g * CPG;
        for (int i = tid; i < CPG * 512; i += 256) {
            int nl = i >> 4;
            int c16 = i & 15;
            __nv_bfloat16 h, l;
            splitf(st[nl][c16], h, l);
            Hh[dst + (size_t)nl * CH + c16] = h;
            Hl[dst + (size_t)nl * CH + c16] = l;
        }
        __syncthreads();
    }
}

// ---------------------------------------------------------------------------
// Row softmax over fp32 logits -> single bf16 prob plane
// ---------------------------------------------------------------------------
__global__ __launch_bounds__(256) void softmax_kernel(
    const float* __restrict__ S, __nv_bfloat16* __restrict__ Sp)
{
    const float* p = S + (size_t)blockIdx.x * NPIX;
    __nv_bfloat16* po = Sp + (size_t)blockIdx.x * NPIX;
    const int t = threadIdx.x;

    float v[4];
    float mx = -1e30f;
    #pragma unroll
    for (int i = 0; i < 4; i++) { v[i] = p[t + i * 256]; mx = fmaxf(mx, v[i]); }
    __shared__ float red[256];
    red[t] = mx;
    __syncthreads();
    for (int st = 128; st > 0; st >>= 1) {
        if (t < st) red[t] = fmaxf(red[t], red[t + st]);
        __syncthreads();
    }
    mx = red[0];
    __syncthreads();
    float sum = 0.f;
    #pragma unroll
    for (int i = 0; i < 4; i++) { v[i] = __expf(v[i] - mx); sum += v[i]; }
    red[t] = sum;
    __syncthreads();
    for (int st = 128; st > 0; st >>= 1) {
        if (t < st) red[t] += red[t + st];
        __syncthreads();
    }
    const float inv = 1.0f / red[0];
    #pragma unroll
    for (int i = 0; i < 4; i++) po[t + i * 256] = __float2bfloat16(v[i] * inv);
}

// ---------------------------------------------------------------------------
// Tensor-core GEMM over bf16 planes:
//   C[m][n] = alpha * sum_k A(m,k)*B(n,k) + bias_row[m] + bias_col[n] (+resid)
// TERMS=3: ah*bh + ah*bl + al*bh ; TERMS=2: ah*bh + ah*bl (A single plane)
// Block 128x128, k-chunk 32, 2-stage cp.async double buffer, 8 warps,
// 2 CTAs/SM. MMA issue order is term-outermost: 16 independent accumulators
// between reuses -> no RAW stalls on the tensor pipe.
// ---------------------------------------------------------------------------
#define TILE_B   10240            // 128 rows * 40 halves * 2B
#define ROWS_H   40               // padded row stride in halves

template<int TERMS, bool OUTF32>
__global__ __launch_bounds__(256, 2) void mma_gemm(
    const __nv_bfloat16* __restrict__ Ah, const __nv_bfloat16* __restrict__ Al,
    const __nv_bfloat16* __restrict__ Bh, const __nv_bfloat16* __restrict__ Bl,
    void* __restrict__ C0, void* __restrict__ C1,
    int N, int K,
    size_t sA, size_t sB, size_t sC,
    const float* __restrict__ bias_row, const float* __restrict__ bias_col,
    const float* __restrict__ resid, size_t sR, float alpha)
{
    constexpr int AP = (TERMS == 3) ? 2 : 1;
    constexpr int NTILES = AP + 2;
    constexpr int STAGE = NTILES * TILE_B;

    extern __shared__ __align__(1024) char smem[];
    const uint32_t sb = smem_u32(smem);

    const int tid  = threadIdx.x;
    const int lane = tid & 31;
    const int warp = tid >> 5;
    const int wm = (warp >> 2) * 64;
    const int wn = (warp & 3) * 32;
    const int m0 = blockIdx.y * 128;
    const int n0 = blockIdx.x * 128;
    const int bz = blockIdx.z;

    const __nv_bfloat16* gA[2];
    gA[0] = Ah + (size_t)bz * sA;
    gA[1] = (TERMS == 3) ? (Al + (size_t)bz * sA) : nullptr;
    const __nv_bfloat16* gB[2];
    gB[0] = Bh + (size_t)bz * sB;
    gB[1] = Bl + (size_t)bz * sB;

    auto issue = [&](int c) {
        const int stg = c & 1;
        const int k0 = c * 32;
        const uint32_t sbase = sb + stg * STAGE;
        #pragma unroll
        for (int i = 0; i < 2; i++) {
            const int idx = tid + i * 256;       // 0..511
            const int r = idx >> 2;
            const int seg = idx & 3;
            const uint32_t soff = r * (ROWS_H * 2) + seg * 16;
            const size_t ga = (size_t)(m0 + r) * K + k0 + seg * 8;
            const size_t gb = (size_t)(n0 + r) * K + k0 + seg * 8;
            #pragma unroll
            for (int t = 0; t < AP; t++)
                cp16(sbase + t * TILE_B + soff, gA[t] + ga);
            #pragma unroll
            for (int t = 0; t < 2; t++)
                cp16(sbase + (AP + t) * TILE_B + soff, gB[t] + gb);
        }
        cp_commit();
    };

    float acc[4][4][4] = {};

    const int nc = K >> 5;
    issue(0);

    const int ar = lane & 15;
    const int ac0 = (lane >> 4) * 8;
    const int br = (lane & 7) + (lane >> 4) * 8;
    const int bc0 = ((lane >> 3) & 1) * 8;

    for (int c = 0; c < nc; c++) {
        cp_wait<0>();
        __syncthreads();
        if (c + 1 < nc) issue(c + 1);

        const int stg = c & 1;
        const __nv_bfloat16* TAh = (const __nv_bfloat16*)(smem + stg * STAGE);
        const __nv_bfloat16* TAl = (const __nv_bfloat16*)(smem + stg * STAGE + TILE_B);
        const __nv_bfloat16* TBh = (const __nv_bfloat16*)(smem + stg * STAGE + AP * TILE_B);
        const __nv_bfloat16* TBl = (const __nv_bfloat16*)(smem + stg * STAGE + (AP + 1) * TILE_B);

        #pragma unroll
        for (int kk = 0; kk < 32; kk += 16) {
            uint32_t ah[4][4], al[4][4];
            uint32_t bh[8], bl[8];
            #pragma unroll
            for (int i = 0; i < 4; i++) {
                ldsm4(ah[i], smem_u32(TAh + (wm + i * 16 + ar) * ROWS_H + kk + ac0));
                if (TERMS == 3)
                    ldsm4(al[i], smem_u32(TAl + (wm + i * 16 + ar) * ROWS_H + kk + ac0));
            }
            #pragma unroll
            for (int jj = 0; jj < 2; jj++) {
                ldsm4(&bh[4 * jj], smem_u32(TBh + (wn + jj * 16 + br) * ROWS_H + kk + bc0));
                ldsm4(&bl[4 * jj], smem_u32(TBl + (wn + jj * 16 + br) * ROWS_H + kk + bc0));
            }
            // term-outermost: 16 independent accumulators between reuses
            #pragma unroll
            for (int i = 0; i < 4; i++)
                #pragma unroll
                for (int j = 0; j < 4; j++)
                    mma16816(acc[i][j], ah[i], &bh[2 * j]);
            #pragma unroll
            for (int i = 0; i < 4; i++)
                #pragma unroll
                for (int j = 0; j < 4; j++)
                    mma16816(acc[i][j], ah[i], &bl[2 * j]);
            if (TERMS == 3) {
                #pragma unroll
                for (int i = 0; i < 4; i++)
                    #pragma unroll
                    for (int j = 0; j < 4; j++)
                        mma16816(acc[i][j], al[i], &bh[2 * j]);
            }
        }
        // no trailing barrier: next iteration's post-wait __syncthreads orders
        // all warps' compute of this chunk before issue() reuses its buffer.
    }

    // ---- epilogue ----
    const int g  = lane >> 2;
    const int t2 = (lane & 3) * 2;
    #pragma unroll
    for (int i = 0; i < 4; i++) {
        const int m = m0 + wm + i * 16 + g;
        const float br0 = bias_row ? bias_row[m] : 0.f;
        const float br1 = bias_row ? bias_row[m + 8] : 0.f;
        #pragma unroll
        for (int j = 0; j < 4; j++) {
            const int n = n0 + wn + j * 8 + t2;
            float bc0v = 0.f, bc1v = 0.f;
            if (bias_col) { bc0v = bias_col[n]; bc1v = bias_col[n + 1]; }
            float v0 = acc[i][j][0] * alpha + br0 + bc0v;
            float v1 = acc[i][j][1] * alpha + br0 + bc1v;
            float v2 = acc[i][j][2] * alpha + br1 + bc0v;
            float v3 = acc[i][j][3] * alpha + br1 + bc1v;
            if (resid) {
                const float* rp = resid + (size_t)bz * sR;
                v0 += rp[(size_t)m * N + n];
                v1 += rp[(size_t)m * N + n + 1];
                v2 += rp[(size_t)(m + 8) * N + n];
                v3 += rp[(size_t)(m + 8) * N + n + 1];
            }
            if (OUTF32) {
                float* C = (float*)C0 + (size_t)bz * sC;
                float2 o0; o0.x = v0; o0.y = v1;
                float2 o1; o1.x = v2; o1.y = v3;
                *(float2*)&C[(size_t)m * N + n] = o0;
                *(float2*)&C[(size_t)(m + 8) * N + n] = o1;
            } else {
                __nv_bfloat16* Ch = (__nv_bfloat16*)C0 + (size_t)bz * sC;
                __nv_bfloat16* Cl = (__nv_bfloat16*)C1 + (size_t)bz * sC;
                __nv_bfloat16 h0, l0, h1, l1, h2, l2, h3, l3;
                splitf(v0, h0, l0); splitf(v1, h1, l1);
                splitf(v2, h2, l2); splitf(v3, h3, l3);
                __nv_bfloat162 hh01; hh01.x = h0; hh01.y = h1;
                __nv_bfloat162 ll01; ll01.x = l0; ll01.y = l1;
                __nv_bfloat162 hh23; hh23.x = h2; hh23.y = h3;
                __nv_bfloat162 ll23; ll23.x = l2; ll23.y = l3;
                *(__nv_bfloat162*)&Ch[(size_t)m * N + n] = hh01;
                *(__nv_bfloat162*)&Cl[(size_t)m * N + n] = ll01;
                *(__nv_bfloat162*)&Ch[(size_t)(m + 8) * N + n] = hh23;
                *(__nv_bfloat162*)&Cl[(size_t)(m + 8) * N + n] = ll23;
            }
        }
    }
}

// ---------------------------------------------------------------------------
// Launch
// ---------------------------------------------------------------------------
extern "C" void kernel_launch(void* const* d_in, const int* in_sizes, int n_in,
                              void* d_out, int out_size)
{
    (void)in_sizes; (void)n_in; (void)out_size;
    const float* x    = (const float*)d_in[0];
    const float* gn_w = (const float*)d_in[1];
    const float* gn_b = (const float*)d_in[2];
    const float* wq   = (const float*)d_in[3];
    const float* bq   = (const float*)d_in[4];
    const float* wk   = (const float*)d_in[5];
    const float* bk   = (const float*)d_in[6];
    const float* wv   = (const float*)d_in[7];
    const float* bv   = (const float*)d_in[8];
    const float* wp   = (const float*)d_in[9];
    const float* bp   = (const float*)d_in[10];
    float* out = (float*)d_out;

    __nv_bfloat16 *Hh, *Hl, *Qh, *Ql, *Kh, *Kl, *Vh, *Vl, *Oh, *Ol, *Wh, *Wl, *Sp;
    float* S;
    cudaGetSymbolAddress((void**)&Hh, g_Hh); cudaGetSymbolAddress((void**)&Hl, g_Hl);
    cudaGetSymbolAddress((void**)&Qh, g_Qh); cudaGetSymbolAddress((void**)&Ql, g_Ql);
    cudaGetSymbolAddress((void**)&Kh, g_Kh); cudaGetSymbolAddress((void**)&Kl, g_Kl);
    cudaGetSymbolAddress((void**)&Vh, g_Vh); cudaGetSymbolAddress((void**)&Vl, g_Vl);
    cudaGetSymbolAddress((void**)&Oh, g_Oh); cudaGetSymbolAddress((void**)&Ol, g_Ol);
    cudaGetSymbolAddress((void**)&Wh, g_Wh); cudaGetSymbolAddress((void**)&Wl, g_Wl);
    cudaGetSymbolAddress((void**)&S,  g_S);  cudaGetSymbolAddress((void**)&Sp, g_Sp);

    const int SM3 = 2 * 4 * TILE_B;  // 81920
    const int SM2 = 2 * 3 * TILE_B;  // 61440
    static bool attr_done = false;
    if (!attr_done) {
        cudaFuncSetAttribute(mma_gemm<3, true>,  cudaFuncAttributeMaxDynamicSharedMemorySize, SM3);
        cudaFuncSetAttribute(mma_gemm<3, false>, cudaFuncAttributeMaxDynamicSharedMemorySize, SM3);
        cudaFuncSetAttribute(mma_gemm<2, false>, cudaFuncAttributeMaxDynamicSharedMemorySize, SM2);
        attr_done = true;
    }

    const size_t WSZ = (size_t)CH * CH;
    const size_t sCN = (size_t)CH * NPIX;
    const size_t sNN = (size_t)NPIX * NPIX;
    const float scale = 0.044194173824159223f; // 512^-0.5

    // 0) pack weights into hi/lo planes
    pack_w_kernel<<<4096, 256>>>(wq, wk, wv, wp, Wh, Wl);

    // 1) GroupNorm -> H^T planes [b][n][c]
    gn_kernel<<<BATCH * NG, 256>>>(x, gn_w, gn_b, Hh, Hl);

    // 2) Q[n][co] = H^T[n][c] . Wq[co][c] + bq  (M=1024,N=512,K=512)
    {
        dim3 grid(CH / 128, NPIX / 128, BATCH);
        mma_gemm<3, false><<<grid, 256, SM3>>>(Hh, Hl, Wh, Wl, Qh, Ql,
            CH, CH, sCN, 0, sCN, nullptr, bq, nullptr, 0, 1.f);
        mma_gemm<3, false><<<grid, 256, SM3>>>(Hh, Hl, Wh + WSZ, Wl + WSZ, Kh, Kl,
            CH, CH, sCN, 0, sCN, nullptr, bk, nullptr, 0, 1.f);
    }
    // 3) V[co][n] = Wv[co][c] . H^T[n][c] + bv  (M=512,N=1024,K=512)
    {
        dim3 grid(NPIX / 128, CH / 128, BATCH);
        mma_gemm<3, false><<<grid, 256, SM3>>>(Wh + 2 * WSZ, Wl + 2 * WSZ, Hh, Hl, Vh, Vl,
            NPIX, CH, 0, sCN, sCN, bv, nullptr, nullptr, 0, 1.f);
    }
    // 4) S[q][k] = scale * Q[q][c] . K[k][c]  (M=N=1024,K=512) fp32
    {
        dim3 grid(NPIX / 128, NPIX / 128, BATCH);
        mma_gemm<3, true><<<grid, 256, SM3>>>(Qh, Ql, Kh, Kl, S, nullptr,
            NPIX, CH, sCN, sCN, sNN, nullptr, nullptr, nullptr, 0, scale);
    }
    // 5) softmax -> bf16 probs
    softmax_kernel<<<BATCH * NPIX, 256>>>(S, Sp);

    // 6) O^T[q][co] = P[q][k] . V[co][k]  (M=1024,N=512,K=1024), 2-term
    {
        dim3 grid(CH / 128, NPIX / 128, BATCH);
        mma_gemm<2, false><<<grid, 256, SM2>>>(Sp, nullptr, Vh, Vl, Oh, Ol,
            CH, NPIX, sNN, sCN, sCN, nullptr, nullptr, nullptr, 0, 1.f);
    }
    // 7) out[co][n] = Wp[co][c] . O^T[n][c] + bp + x  (M=512,N=1024,K=512)
    {
        dim3 grid(NPIX / 128, CH / 128, BATCH);
        mma_gemm<3, true><<<grid, 256, SM3>>>(Wh + 3 * WSZ, Wl + 3 * WSZ, Oh, Ol, out, nullptr,
            NPIX, CH, 0, sCN, sCN, bp, nullptr, x, sCN, 1.f);
    }
}

// round 7
// speedup vs baseline: 5.0097x; 1.5227x over previous
#include <cuda_runtime.h>
#include <cuda_bf16.h>
#include <cstdint>
#include <cstddef>

#define BATCH 32
#define CH    512
#define NPIX  1024
#define NG    32
#define CPG   16
#define EPS   1e-6f

// ---------------------------------------------------------------------------
// Scratch: activations single bf16 plane; weights split hi/lo.
// ---------------------------------------------------------------------------
#define SZ_CN ((size_t)BATCH * NPIX * CH)
#define SZ_NN ((size_t)BATCH * NPIX * NPIX)

__device__ __nv_bfloat16 g_Hh[SZ_CN];     // H^T [b][n][c]
__device__ __nv_bfloat16 g_Qh[SZ_CN];     // Q   [b][n][co]
__device__ __nv_bfloat16 g_Kh[SZ_CN];     // K   [b][n][co]
__device__ __nv_bfloat16 g_Vh[SZ_CN];     // V   [b][co][n]
__device__ float         g_S [SZ_NN];     // logits fp32
__device__ __nv_bfloat16 g_Sp[SZ_NN];     // probs bf16
__device__ __nv_bfloat16 g_Oh[SZ_CN];     // O^T [b][q][co]
__device__ __nv_bfloat16 g_Wh[4 * (size_t)CH * CH], g_Wl[4 * (size_t)CH * CH];

// ---------------------------------------------------------------------------
// Helpers
// ---------------------------------------------------------------------------
__device__ __forceinline__ uint32_t smem_u32(const void* p) {
    return (uint32_t)__cvta_generic_to_shared(p);
}
__device__ __forceinline__ void ldsm4(uint32_t r[4], uint32_t a) {
    asm volatile("ldmatrix.sync.aligned.m8n8.x4.shared.b16 {%0,%1,%2,%3}, [%4];"
        : "=r"(r[0]), "=r"(r[1]), "=r"(r[2]), "=r"(r[3]) : "r"(a));
}
__device__ __forceinline__ void mma16816(float d[4], const uint32_t a[4], const uint32_t* b) {
    asm volatile(
        "mma.sync.aligned.m16n8k16.row.col.f32.bf16.bf16.f32 "
        "{%0,%1,%2,%3}, {%4,%5,%6,%7}, {%8,%9}, {%0,%1,%2,%3};"
        : "+f"(d[0]), "+f"(d[1]), "+f"(d[2]), "+f"(d[3])
        : "r"(a[0]), "r"(a[1]), "r"(a[2]), "r"(a[3]), "r"(b[0]), "r"(b[1]));
}
__device__ __forceinline__ void cp16(uint32_t s, const void* g) {
    asm volatile("cp.async.cg.shared.global [%0], [%1], 16;" :: "r"(s), "l"(g));
}
__device__ __forceinline__ void cp_commit() {
    asm volatile("cp.async.commit_group;" ::: "memory");
}
template<int n>
__device__ __forceinline__ void cp_wait() {
    asm volatile("cp.async.wait_group %0;" :: "n"(n) : "memory");
}
__device__ __forceinline__ void splitf(float x, __nv_bfloat16& h, __nv_bfloat16& l) {
    h = __float2bfloat16(x);
    l = __float2bfloat16(x - __bfloat162float(h));
}

// ---------------------------------------------------------------------------
// Weight pack: 4 x [512][512] fp32 -> hi/lo planes
// ---------------------------------------------------------------------------
__global__ __launch_bounds__(256) void pack_w_kernel(
    const float* __restrict__ a0, const float* __restrict__ a1,
    const float* __restrict__ a2, const float* __restrict__ a3,
    __nv_bfloat16* __restrict__ oh, __nv_bfloat16* __restrict__ ol)
{
    int i = blockIdx.x * 256 + threadIdx.x;
    int t = i >> 18;
    int j = i & 262143;
    const float* src = (t == 0) ? a0 : (t == 1) ? a1 : (t == 2) ? a2 : a3;
    __nv_bfloat16 h, l;
    splitf(src[j], h, l);
    oh[i] = h; ol[i] = l;
}

// ---------------------------------------------------------------------------
// GroupNorm -> transposed single bf16 plane H^T[b][n][c]
// ---------------------------------------------------------------------------
__global__ __launch_bounds__(256) void gn_kernel(
    const float* __restrict__ x, const float* __restrict__ w,
    const float* __restrict__ b, __nv_bfloat16* __restrict__ Hh)
{
    const int bg = blockIdx.x;
    const int batch = bg >> 5;
    const int g = bg & 31;
    const int tid = threadIdx.x;
    const float* xp = x + ((size_t)batch * CH + (size_t)g * CPG) * NPIX;

    float s = 0.f, ss = 0.f;
    for (int i = tid; i < CPG * NPIX; i += 256) {
        float v = xp[i];
        s += v; ss += v * v;
    }
    __shared__ float sh_s[256], sh_ss[256];
    sh_s[tid] = s; sh_ss[tid] = ss;
    __syncthreads();
    for (int st = 128; st > 0; st >>= 1) {
        if (tid < st) { sh_s[tid] += sh_s[tid + st]; sh_ss[tid] += sh_ss[tid + st]; }
        __syncthreads();
    }
    const float mean = sh_s[0] * (1.0f / (CPG * NPIX));
    const float var  = sh_ss[0] * (1.0f / (CPG * NPIX)) - mean * mean;
    const float inv  = rsqrtf(var + EPS);

    __shared__ float st[512][17];

    for (int half = 0; half < 2; half++) {
        for (int i = tid; i < CPG * 512; i += 256) {
            int c16 = i >> 9;
            int nl  = i & 511;
            int c   = g * CPG + c16;
            float v = (xp[c16 * NPIX + half * 512 + nl] - mean) * inv;
            st[nl][c16] = v * w[c] + b[c];
        }
        __syncthreads();
        size_t dst = ((size_t)batch * NPIX + half * 512) * CH + g * CPG;
        for (int i = tid; i < CPG * 512; i += 256) {
            int nl = i >> 4;
            int c16 = i & 15;
            Hh[dst + (size_t)nl * CH + c16] = __float2bfloat16(st[nl][c16]);
        }
        __syncthreads();
    }
}

// ---------------------------------------------------------------------------
// Row softmax over fp32 logits -> single bf16 prob plane
// ---------------------------------------------------------------------------
__global__ __launch_bounds__(256) void softmax_kernel(
    const float* __restrict__ S, __nv_bfloat16* __restrict__ Sp)
{
    const float* p = S + (size_t)blockIdx.x * NPIX;
    __nv_bfloat16* po = Sp + (size_t)blockIdx.x * NPIX;
    const int t = threadIdx.x;

    float v[4];
    float mx = -1e30f;
    #pragma unroll
    for (int i = 0; i < 4; i++) { v[i] = p[t + i * 256]; mx = fmaxf(mx, v[i]); }
    __shared__ float red[256];
    red[t] = mx;
    __syncthreads();
    for (int st = 128; st > 0; st >>= 1) {
        if (t < st) red[t] = fmaxf(red[t], red[t + st]);
        __syncthreads();
    }
    mx = red[0];
    __syncthreads();
    float sum = 0.f;
    #pragma unroll
    for (int i = 0; i < 4; i++) { v[i] = __expf(v[i] - mx); sum += v[i]; }
    red[t] = sum;
    __syncthreads();
    for (int st = 128; st > 0; st >>= 1) {
        if (t < st) red[t] += red[t + st];
        __syncthreads();
    }
    const float inv = 1.0f / red[0];
    #pragma unroll
    for (int i = 0; i < 4; i++) po[t + i * 256] = __float2bfloat16(v[i] * inv);
}

// ---------------------------------------------------------------------------
// Tensor-core GEMM:
//   C[m][n] = alpha * sum_k A(m,k)*B(n,k) + bias_row[m] + bias_col[n] (+resid)
// PA/PB: number of bf16 planes per operand (2 = hi/lo split).
// Terms computed: a0*b0 (+ a0*b1 if PB==2) (+ a1*b0 if PA==2).
// OUTF32: fp32 out; else single bf16 plane.
// Block 128x128, k-chunk 32, 2-stage cp.async, 8 warps, 2 CTAs/SM.
// ---------------------------------------------------------------------------
#define TILE_B   10240            // 128 rows * 40 halves * 2B
#define ROWS_H   40

template<int PA, int PB, bool OUTF32>
__global__ __launch_bounds__(256, 2) void mma_gemm(
    const __nv_bfloat16* __restrict__ Ah, const __nv_bfloat16* __restrict__ Al,
    const __nv_bfloat16* __restrict__ Bh, const __nv_bfloat16* __restrict__ Bl,
    void* __restrict__ C0,
    int N, int K,
    size_t sA, size_t sB, size_t sC,
    const float* __restrict__ bias_row, const float* __restrict__ bias_col,
    const float* __restrict__ resid, size_t sR, float alpha)
{
    constexpr int NTILES = PA + PB;
    constexpr int STAGE = NTILES * TILE_B;

    extern __shared__ __align__(1024) char smem[];
    const uint32_t sb = smem_u32(smem);

    const int tid  = threadIdx.x;
    const int lane = tid & 31;
    const int warp = tid >> 5;
    const int wm = (warp >> 2) * 64;
    const int wn = (warp & 3) * 32;
    const int m0 = blockIdx.y * 128;
    const int n0 = blockIdx.x * 128;
    const int bz = blockIdx.z;

    const __nv_bfloat16* gA[2];
    gA[0] = Ah + (size_t)bz * sA;
    gA[1] = (PA == 2) ? (Al + (size_t)bz * sA) : nullptr;
    const __nv_bfloat16* gB[2];
    gB[0] = Bh + (size_t)bz * sB;
    gB[1] = (PB == 2) ? (Bl + (size_t)bz * sB) : nullptr;

    auto issue = [&](int c) {
        const int stg = c & 1;
        const int k0 = c * 32;
        const uint32_t sbase = sb + stg * STAGE;
        #pragma unroll
        for (int i = 0; i < 2; i++) {
            const int idx = tid + i * 256;       // 0..511
            const int r = idx >> 2;
            const int seg = idx & 3;
            const uint32_t soff = r * (ROWS_H * 2) + seg * 16;
            const size_t ga = (size_t)(m0 + r) * K + k0 + seg * 8;
            const size_t gb = (size_t)(n0 + r) * K + k0 + seg * 8;
            #pragma unroll
            for (int t = 0; t < PA; t++)
                cp16(sbase + t * TILE_B + soff, gA[t] + ga);
            #pragma unroll
            for (int t = 0; t < PB; t++)
                cp16(sbase + (PA + t) * TILE_B + soff, gB[t] + gb);
        }
        cp_commit();
    };

    float acc[4][4][4] = {};

    const int nc = K >> 5;
    issue(0);

    const int ar = lane & 15;
    const int ac0 = (lane >> 4) * 8;
    const int br = (lane & 7) + (lane >> 4) * 8;
    const int bc0 = ((lane >> 3) & 1) * 8;

    for (int c = 0; c < nc; c++) {
        cp_wait<0>();
        __syncthreads();
        if (c + 1 < nc) issue(c + 1);

        const int stg = c & 1;
        const __nv_bfloat16* TA0 = (const __nv_bfloat16*)(smem + stg * STAGE);
        const __nv_bfloat16* TA1 = (const __nv_bfloat16*)(smem + stg * STAGE + TILE_B);
        const __nv_bfloat16* TB0 = (const __nv_bfloat16*)(smem + stg * STAGE + PA * TILE_B);
        const __nv_bfloat16* TB1 = (const __nv_bfloat16*)(smem + stg * STAGE + (PA + 1) * TILE_B);

        #pragma unroll
        for (int kk = 0; kk < 32; kk += 16) {
            uint32_t a0[4][4], a1[4][4];
            uint32_t b0[8], b1[8];
            #pragma unroll
            for (int i = 0; i < 4; i++) {
                ldsm4(a0[i], smem_u32(TA0 + (wm + i * 16 + ar) * ROWS_H + kk + ac0));
                if (PA == 2)
                    ldsm4(a1[i], smem_u32(TA1 + (wm + i * 16 + ar) * ROWS_H + kk + ac0));
            }
            #pragma unroll
            for (int jj = 0; jj < 2; jj++) {
                ldsm4(&b0[4 * jj], smem_u32(TB0 + (wn + jj * 16 + br) * ROWS_H + kk + bc0));
                if (PB == 2)
                    ldsm4(&b1[4 * jj], smem_u32(TB1 + (wn + jj * 16 + br) * ROWS_H + kk + bc0));
            }
            #pragma unroll
            for (int i = 0; i < 4; i++)
                #pragma unroll
                for (int j = 0; j < 4; j++)
                    mma16816(acc[i][j], a0[i], &b0[2 * j]);
            if (PB == 2) {
                #pragma unroll
                for (int i = 0; i < 4; i++)
                    #pragma unroll
                    for (int j = 0; j < 4; j++)
                        mma16816(acc[i][j], a0[i], &b1[2 * j]);
            }
            if (PA == 2) {
                #pragma unroll
                for (int i = 0; i < 4; i++)
                    #pragma unroll
                    for (int j = 0; j < 4; j++)
                        mma16816(acc[i][j], a1[i], &b0[2 * j]);
            }
        }
    }

    // ---- epilogue ----
    const int g  = lane >> 2;
    const int t2 = (lane & 3) * 2;
    #pragma unroll
    for (int i = 0; i < 4; i++) {
        const int m = m0 + wm + i * 16 + g;
        const float br0 = bias_row ? bias_row[m] : 0.f;
        const float br1 = bias_row ? bias_row[m + 8] : 0.f;
        #pragma unroll
        for (int j = 0; j < 4; j++) {
            const int n = n0 + wn + j * 8 + t2;
            float bc0v = 0.f, bc1v = 0.f;
            if (bias_col) { bc0v = bias_col[n]; bc1v = bias_col[n + 1]; }
            float v0 = acc[i][j][0] * alpha + br0 + bc0v;
            float v1 = acc[i][j][1] * alpha + br0 + bc1v;
            float v2 = acc[i][j][2] * alpha + br1 + bc0v;
            float v3 = acc[i][j][3] * alpha + br1 + bc1v;
            if (resid) {
                const float* rp = resid + (size_t)bz * sR;
                v0 += rp[(size_t)m * N + n];
                v1 += rp[(size_t)m * N + n + 1];
                v2 += rp[(size_t)(m + 8) * N + n];
                v3 += rp[(size_t)(m + 8) * N + n + 1];
            }
            if (OUTF32) {
                float* C = (float*)C0 + (size_t)bz * sC;
                float2 o0; o0.x = v0; o0.y = v1;
                float2 o1; o1.x = v2; o1.y = v3;
                *(float2*)&C[(size_t)m * N + n] = o0;
                *(float2*)&C[(size_t)(m + 8) * N + n] = o1;
            } else {
                __nv_bfloat16* Ch = (__nv_bfloat16*)C0 + (size_t)bz * sC;
                __nv_bfloat162 hh01, hh23;
                hh01.x = __float2bfloat16(v0); hh01.y = __float2bfloat16(v1);
                hh23.x = __float2bfloat16(v2); hh23.y = __float2bfloat16(v3);
                *(__nv_bfloat162*)&Ch[(size_t)m * N + n] = hh01;
                *(__nv_bfloat162*)&Ch[(size_t)(m + 8) * N + n] = hh23;
            }
        }
    }
}

// ---------------------------------------------------------------------------
// Launch
// ---------------------------------------------------------------------------
extern "C" void kernel_launch(void* const* d_in, const int* in_sizes, int n_in,
                              void* d_out, int out_size)
{
    (void)in_sizes; (void)n_in; (void)out_size;
    const float* x    = (const float*)d_in[0];
    const float* gn_w = (const float*)d_in[1];
    const float* gn_b = (const float*)d_in[2];
    const float* wq   = (const float*)d_in[3];
    const float* bq   = (const float*)d_in[4];
    const float* wk   = (const float*)d_in[5];
    const float* bk   = (const float*)d_in[6];
    const float* wv   = (const float*)d_in[7];
    const float* bv   = (const float*)d_in[8];
    const float* wp   = (const float*)d_in[9];
    const float* bp   = (const float*)d_in[10];
    float* out = (float*)d_out;

    __nv_bfloat16 *Hh, *Qh, *Kh, *Vh, *Oh, *Wh, *Wl, *Sp;
    float* S;
    cudaGetSymbolAddress((void**)&Hh, g_Hh);
    cudaGetSymbolAddress((void**)&Qh, g_Qh);
    cudaGetSymbolAddress((void**)&Kh, g_Kh);
    cudaGetSymbolAddress((void**)&Vh, g_Vh);
    cudaGetSymbolAddress((void**)&Oh, g_Oh);
    cudaGetSymbolAddress((void**)&Wh, g_Wh); cudaGetSymbolAddress((void**)&Wl, g_Wl);
    cudaGetSymbolAddress((void**)&S,  g_S);  cudaGetSymbolAddress((void**)&Sp, g_Sp);

    const int SM3 = 2 * 3 * TILE_B;  // 61440 (PA+PB==3)
    const int SM2 = 2 * 2 * TILE_B;  // 40960 (PA+PB==2)
    static bool attr_done = false;
    if (!attr_done) {
        cudaFuncSetAttribute((const void*)mma_gemm<1, 2, false>, cudaFuncAttributeMaxDynamicSharedMemorySize, SM3);
        cudaFuncSetAttribute((const void*)mma_gemm<2, 1, false>, cudaFuncAttributeMaxDynamicSharedMemorySize, SM3);
        cudaFuncSetAttribute((const void*)mma_gemm<2, 1, true>,  cudaFuncAttributeMaxDynamicSharedMemorySize, SM3);
        cudaFuncSetAttribute((const void*)mma_gemm<1, 1, true>,  cudaFuncAttributeMaxDynamicSharedMemorySize, SM2);
        cudaFuncSetAttribute((const void*)mma_gemm<1, 1, false>, cudaFuncAttributeMaxDynamicSharedMemorySize, SM2);
        attr_done = true;
    }

    const size_t WSZ = (size_t)CH * CH;
    const size_t sCN = (size_t)CH * NPIX;
    const size_t sNN = (size_t)NPIX * NPIX;
    const float scale = 0.044194173824159223f; // 512^-0.5

    // 0) pack weights into hi/lo planes
    pack_w_kernel<<<4096, 256>>>(wq, wk, wv, wp, Wh, Wl);

    // 1) GroupNorm -> H^T bf16 [b][n][c]
    gn_kernel<<<BATCH * NG, 256>>>(x, gn_w, gn_b, Hh);

    // 2) Q[n][co] = H^T[n][c] . Wq[co][c] + bq  (2-term: H x {Wh,Wl})
    {
        dim3 grid(CH / 128, NPIX / 128, BATCH);
        mma_gemm<1, 2, false><<<grid, 256, SM3>>>(Hh, nullptr, Wh, Wl, Qh,
            CH, CH, sCN, 0, sCN, nullptr, bq, nullptr, 0, 1.f);
        mma_gemm<1, 2, false><<<grid, 256, SM3>>>(Hh, nullptr, Wh + WSZ, Wl + WSZ, Kh,
            CH, CH, sCN, 0, sCN, nullptr, bk, nullptr, 0, 1.f);
    }
    // 3) V[co][n] = Wv[co][c] . H^T[n][c] + bv  (2-term: {Wh,Wl} x H)
    {
        dim3 grid(NPIX / 128, CH / 128, BATCH);
        mma_gemm<2, 1, false><<<grid, 256, SM3>>>(Wh + 2 * WSZ, Wl + 2 * WSZ, Hh, nullptr, Vh,
            NPIX, CH, 0, sCN, sCN, bv, nullptr, nullptr, 0, 1.f);
    }
    // 4) S[q][k] = scale * Q[q][c] . K[k][c]  (1-term) fp32
    {
        dim3 grid(NPIX / 128, NPIX / 128, BATCH);
        mma_gemm<1, 1, true><<<grid, 256, SM2>>>(Qh, nullptr, Kh, nullptr, S,
            NPIX, CH, sCN, sCN, sNN, nullptr, nullptr, nullptr, 0, scale);
    }
    // 5) softmax -> bf16 probs
    softmax_kernel<<<BATCH * NPIX, 256>>>(S, Sp);

    // 6) O^T[q][co] = P[q][k] . V[co][k]  (1-term)
    {
        dim3 grid(CH / 128, NPIX / 128, BATCH);
        mma_gemm<1, 1, false><<<grid, 256, SM2>>>(Sp, nullptr, Vh, nullptr, Oh,
            CH, NPIX, sNN, sCN, sCN, nullptr, nullptr, nullptr, 0, 1.f);
    }
    // 7) out[co][n] = Wp[co][c] . O^T[n][c] + bp + x  (2-term)
    {
        dim3 grid(NPIX / 128, CH / 128, BATCH);
        mma_gemm<2, 1, true><<<grid, 256, SM3>>>(Wh + 3 * WSZ, Wl + 3 * WSZ, Oh, nullptr, out,
            NPIX, CH, 0, sCN, sCN, bp, nullptr, x, sCN, 1.f);
    }
}